// round 1
// baseline (speedup 1.0000x reference)
#include <cuda_runtime.h>
#include <math.h>

#define B_   4096
#define L_   50
#define K_   10
#define LI_  20
#define D_   64
#define C_   10
#define NIP1 50001

// ---------------- scratch (static device globals; no allocation) -------------
__device__ float g_ju[NIP1 * D_];
__device__ float g_jv[NIP1 * D_];
__device__ float g_hu[B_ * D_];
__device__ float g_s1[B_ * K_];
__device__ float g_s2[B_ * K_];
__device__ float g_d1[B_ * K_];
__device__ float g_d2[B_ * K_];
__device__ float g_cs[4 * K_];   // [0:10) max1, [10:20) sum1, [20:30) max2, [30:40) sum2

__device__ __forceinline__ float wred(float v) {
#pragma unroll
    for (int o = 16; o; o >>= 1) v += __shfl_xor_sync(0xffffffffu, v, o);
    return v;
}
__device__ __forceinline__ float lrelu(float x) { return x >= 0.f ? x : 0.01f * x; }

// ============================================================================
// K1: ju_all = [item_emb | i_class] @ W1 + b1 ; jv_all = same with W3/b3
// ============================================================================
__global__ void k_precompute(const float* __restrict__ item_emb,
                             const float* __restrict__ i_class,
                             const float* __restrict__ W1, const float* __restrict__ b1,
                             const float* __restrict__ W3, const float* __restrict__ b3) {
    __shared__ float W1s[74][64];
    __shared__ float W3s[74][64];
    __shared__ float xs[4][74];
    int tid = threadIdx.x;
    for (int i = tid; i < 74 * 64; i += 256) {
        W1s[i / 64][i % 64] = W1[i];
        W3s[i / 64][i % 64] = W3[i];
    }
    int row0 = blockIdx.x * 4;
    for (int i = tid; i < 4 * 74; i += 256) {
        int rr = i / 74, k = i % 74;
        int row = row0 + rr;
        float v = 0.f;
        if (row < NIP1) v = (k < 64) ? item_emb[row * 64 + k] : i_class[row * 10 + (k - 64)];
        xs[rr][k] = v;
    }
    __syncthreads();
    int r = tid >> 6, c = tid & 63;
    int row = row0 + r;
    if (row < NIP1) {
        float a1 = b1[c], a3 = b3[c];
#pragma unroll
        for (int k = 0; k < 74; k++) {
            float x = xs[r][k];
            a1 = fmaf(x, W1s[k][c], a1);
            a3 = fmaf(x, W3s[k][c], a3);
        }
        g_ju[row * 64 + c] = a1;
        g_jv[row * 64 + c] = a3;
    }
}

// ============================================================================
// K2: LSTM. 128 blocks x 32 rows, 256 threads.
// Thread (rg=tid/64, cell=tid%64): 8 rows (rg*8..+7), cols {cell, cell+64,
// cell+128, cell+192} = all 4 gates of cell `cell` -> c stays in registers.
// Weights smem-permuted: Wp[k][cell*4+g] = W[k][cell + 64*g].
// Activations transposed: xs/hs[k or cell][row], pad 36.
// ============================================================================
#define LSTM_SMEM ((128*256 + 64*36 + 64*36) * 4 + 32 * L_ * 4)

__global__ void __launch_bounds__(256, 1)
k_lstm(const int* __restrict__ u_items, const int* __restrict__ u_items_mask,
       const float* __restrict__ Wih, const float* __restrict__ Whh,
       const float* __restrict__ bih, const float* __restrict__ bhh) {
    extern __shared__ float sm[];
    float* Wp  = sm;                  // 128*256
    float* xs  = Wp + 128 * 256;      // 64*36
    float* hs  = xs + 64 * 36;        // 64*36
    int*   idxs = (int*)(hs + 64 * 36); // 32*50
    __shared__ int s_max;

    int tid = threadIdx.x;
    int base = blockIdx.x * 32;

    if (tid == 0) s_max = 0;
    // permuted weight stage
    for (int i = tid; i < 128 * 256; i += 256) {
        int k = i >> 8, jp = i & 255;
        int cc = jp >> 2, g = jp & 3;
        int j = cc + 64 * g;
        Wp[i] = (k < 64) ? Wih[k * 256 + j] : Whh[(k - 64) * 256 + j];
    }
    for (int i = tid; i < 64 * 36; i += 256) hs[i] = 0.f;
    for (int i = tid; i < 32 * L_; i += 256) {
        int r = i / L_, t = i % L_;
        idxs[r * L_ + t] = u_items[(base + r) * L_ + t];
    }
    int cell = tid & 63;
    int rg = tid >> 6;
    int msk[8];
    int mm = 0;
#pragma unroll
    for (int rr = 0; rr < 8; rr++) {
        msk[rr] = u_items_mask[base + rg * 8 + rr];
        mm = max(mm, msk[rr]);
    }
    __syncthreads();
    atomicMax(&s_max, mm);
    float bsum[4];
#pragma unroll
    for (int g = 0; g < 4; g++) bsum[g] = bih[cell + 64 * g] + bhh[cell + 64 * g];
    float c_reg[8];
#pragma unroll
    for (int rr = 0; rr < 8; rr++) c_reg[rr] = 0.f;
    __syncthreads();
    int maxm = s_max;

    int grow = tid & 31, gk8 = tid >> 5;   // gather assignment
    int abase = rg * 8;

    for (int t = 0; t < maxm; t++) {
        // gather x_t (transposed into xs[k][row])
        {
            int idx = idxs[grow * L_ + t];
            const float4* src = (const float4*)(g_ju + idx * 64 + gk8 * 8);
            float4 v0 = src[0], v1 = src[1];
            xs[(gk8 * 8 + 0) * 36 + grow] = v0.x;
            xs[(gk8 * 8 + 1) * 36 + grow] = v0.y;
            xs[(gk8 * 8 + 2) * 36 + grow] = v0.z;
            xs[(gk8 * 8 + 3) * 36 + grow] = v0.w;
            xs[(gk8 * 8 + 4) * 36 + grow] = v1.x;
            xs[(gk8 * 8 + 5) * 36 + grow] = v1.y;
            xs[(gk8 * 8 + 6) * 36 + grow] = v1.z;
            xs[(gk8 * 8 + 7) * 36 + grow] = v1.w;
        }
        __syncthreads();

        float acc[8][4];
#pragma unroll
        for (int rr = 0; rr < 8; rr++) {
            acc[rr][0] = 0.f; acc[rr][1] = 0.f; acc[rr][2] = 0.f; acc[rr][3] = 0.f;
        }
        const float* Wx = Wp;
        const float* Wh = Wp + 64 * 256;
#pragma unroll 8
        for (int k = 0; k < 64; k++) {
            float4 w  = *(const float4*)(Wx + k * 256 + (cell << 2));
            float4 a0 = *(const float4*)(xs + k * 36 + abase);
            float4 a1 = *(const float4*)(xs + k * 36 + abase + 4);
            float ar[8] = {a0.x, a0.y, a0.z, a0.w, a1.x, a1.y, a1.z, a1.w};
#pragma unroll
            for (int rr = 0; rr < 8; rr++) {
                acc[rr][0] = fmaf(ar[rr], w.x, acc[rr][0]);
                acc[rr][1] = fmaf(ar[rr], w.y, acc[rr][1]);
                acc[rr][2] = fmaf(ar[rr], w.z, acc[rr][2]);
                acc[rr][3] = fmaf(ar[rr], w.w, acc[rr][3]);
            }
        }
#pragma unroll 8
        for (int k = 0; k < 64; k++) {
            float4 w  = *(const float4*)(Wh + k * 256 + (cell << 2));
            float4 a0 = *(const float4*)(hs + k * 36 + abase);
            float4 a1 = *(const float4*)(hs + k * 36 + abase + 4);
            float ar[8] = {a0.x, a0.y, a0.z, a0.w, a1.x, a1.y, a1.z, a1.w};
#pragma unroll
            for (int rr = 0; rr < 8; rr++) {
                acc[rr][0] = fmaf(ar[rr], w.x, acc[rr][0]);
                acc[rr][1] = fmaf(ar[rr], w.y, acc[rr][1]);
                acc[rr][2] = fmaf(ar[rr], w.z, acc[rr][2]);
                acc[rr][3] = fmaf(ar[rr], w.w, acc[rr][3]);
            }
        }
        __syncthreads();   // GEMM reads of hs done before rewrite

#pragma unroll
        for (int rr = 0; rr < 8; rr++) {
            float gi = acc[rr][0] + bsum[0];
            float gf = acc[rr][1] + bsum[1];
            float gg = acc[rr][2] + bsum[2];
            float go = acc[rr][3] + bsum[3];
            float si = 1.f / (1.f + expf(-gi));
            float sf = 1.f / (1.f + expf(-gf));
            float so = 1.f / (1.f + expf(-go));
            float c = sf * c_reg[rr] + si * tanhf(gg);
            c_reg[rr] = c;
            float h = so * tanhf(c);
            int row = rg * 8 + rr;
            hs[cell * 36 + row] = h;
            if (t == msk[rr] - 1) g_hu[(base + row) * 64 + cell] = h;
        }
        // hs writes ordered before next GEMM by the sync after the next gather
    }
}

// ============================================================================
// K3: per-row user stage. 8 warps = 8 rows per block, grid 512.
// Produces s1,s2 and d{1,2}[b,k] = dot(zsum[b], Fi{1,2}[b,k]).
// ============================================================================
#define USER_SMEM ((192*64*2 + 256 + 8*192) * 4)

__global__ void __launch_bounds__(256)
k_user(const int* __restrict__ users, const int* __restrict__ items,
       const int* __restrict__ u_frids, const int* __restrict__ u_frids_mask,
       const int* __restrict__ u_frids_items, const int* __restrict__ F_i,
       const float* __restrict__ user_emb, const float* __restrict__ item_emb,
       const float* __restrict__ W2, const float* __restrict__ b2,
       const float* __restrict__ W4, const float* __restrict__ b4,
       const float* __restrict__ W5, const float* __restrict__ b5,
       const float* __restrict__ W6, const float* __restrict__ b6,
       const float* __restrict__ lambdas) {
    extern __shared__ float sm[];
    float* W2s = sm;                 // 192*64
    float* W5s = W2s + 192 * 64;     // 192*64
    float* W4s = W5s + 192 * 64;     // 128
    float* W6s = W4s + 128;          // 128
    float* zb  = W6s + 128;          // 8*192

    int tid = threadIdx.x;
    for (int i = tid; i < 192 * 64; i += 256) { W2s[i] = W2[i]; W5s[i] = W5[i]; }
    for (int i = tid; i < 128; i += 256) { W4s[i] = W4[i]; W6s[i] = W6[i]; }
    __syncthreads();

    int w = tid >> 5, lane = tid & 31;
    int row = blockIdx.x * 8 + w;
    int c0 = lane * 2;
    float l0 = lambdas[0], l1 = lambdas[1], l2 = lambdas[2], l3 = lambdas[3];
    float b4v = b4[0], b6v = b6[0];

    int usr = users[row], itm = items[row];
    float2 u2  = *(const float2*)(user_emb + usr * 64 + c0);
    float2 ie2 = *(const float2*)(item_emb + itm * 64 + c0);
    float2 hu2 = *(const float2*)(g_hu + row * 64 + c0);

    float du = wred(u2.x * W4s[c0] + u2.y * W4s[c0 + 1]);

    float at[K_];
#pragma unroll
    for (int k = 0; k < K_; k++) {
        int fid = u_frids[row * K_ + k];
        float2 v2 = *(const float2*)(user_emb + fid * 64 + c0);
        float s = wred(v2.x * W4s[64 + c0] + v2.y * W4s[65 + c0]);
        at[k] = lrelu(du + s + b4v);
    }
    int fm = u_frids_mask[row];
    float mx = -1e30f;
#pragma unroll
    for (int k = 0; k < K_; k++) if (k < fm) mx = fmaxf(mx, at[k]);
    float se = 0.f, ev[K_];
#pragma unroll
    for (int k = 0; k < K_; k++) { ev[k] = (k < fm) ? expf(at[k] - mx) : 0.f; se += ev[k]; }
    float inv = 1.f / (se * (float)fm);

    // su = sum_k (auv_k/fm) * sum_li jv_all[...]
    float sux = 0.f, suy = 0.f;
#pragma unroll
    for (int k = 0; k < K_; k++) {
        if (k < fm) {
            float px = 0.f, py = 0.f;
            const int* ip = u_frids_items + (row * K_ + k) * LI_;
#pragma unroll 4
            for (int li = 0; li < LI_; li++) {
                int idx = ip[li];
                float2 j2 = *(const float2*)(g_jv + idx * 64 + c0);
                px += j2.x; py += j2.y;
            }
            float wk = ev[k] * inv;
            sux = fmaf(wk, px, sux);
            suy = fmaf(wk, py, suy);
        }
    }

    // hui = [hu, ie, hu*ie] @ W2 + b2
    float* z = zb + w * 192;
    z[c0] = hu2.x; z[c0 + 1] = hu2.y;
    z[64 + c0] = ie2.x; z[64 + c0 + 1] = ie2.y;
    z[128 + c0] = hu2.x * ie2.x; z[128 + c0 + 1] = hu2.y * ie2.y;
    __syncwarp();
    float huix = b2[c0], huiy = b2[c0 + 1];
#pragma unroll 8
    for (int k = 0; k < 192; k++) {
        float x = z[k];
        huix = fmaf(x, W2s[k * 64 + c0], huix);
        huiy = fmaf(x, W2s[k * 64 + c0 + 1], huiy);
    }
    __syncwarp();
    // sui = [su, ie, su*ie] @ W5 + b5 (ie slot unchanged)
    z[c0] = sux; z[c0 + 1] = suy;
    z[128 + c0] = sux * ie2.x; z[128 + c0 + 1] = suy * ie2.y;
    __syncwarp();
    float suix = b5[c0], suiy = b5[c0 + 1];
#pragma unroll 8
    for (int k = 0; k < 192; k++) {
        float x = z[k];
        suix = fmaf(x, W5s[k * 64 + c0], suix);
        suiy = fmaf(x, W5s[k * 64 + c0 + 1], suiy);
    }

    float zsx = l0 * hu2.x + l1 * huix + l2 * sux + l3 * suix;
    float zsy = l0 * hu2.y + l1 * huiy + l2 * suy + l3 * suiy;

    float di = wred(ie2.x * W6s[c0] + ie2.y * W6s[c0 + 1]);

#pragma unroll
    for (int s = 0; s < 2; s++) {
#pragma unroll
        for (int k = 0; k < K_; k++) {
            int fi = F_i[(row * 2 + s) * K_ + k];
            float2 f2 = *(const float2*)(item_emb + fi * 64 + c0);
            float sv = wred(f2.x * W6s[64 + c0] + f2.y * W6s[65 + c0]);
            float dv = wred(f2.x * zsx + f2.y * zsy);
            if (lane == 0) {
                float* sp = s ? g_s2 : g_s1;
                float* dp = s ? g_d2 : g_d1;
                sp[row * K_ + k] = lrelu(di + sv + b6v);
                dp[row * K_ + k] = dv;
            }
        }
    }
}

// ============================================================================
// K4: per-column (axis=0) softmax stats for s1/s2. 20 blocks.
// ============================================================================
__global__ void k_cstat() {
    int sel = blockIdx.x / K_;
    int k = blockIdx.x % K_;
    const float* s = sel ? g_s2 : g_s1;
    __shared__ float red[256];
    int tid = threadIdx.x;
    float mx = -1e30f;
    for (int i = tid; i < B_; i += 256) mx = fmaxf(mx, s[i * K_ + k]);
    red[tid] = mx; __syncthreads();
    for (int o = 128; o; o >>= 1) { if (tid < o) red[tid] = fmaxf(red[tid], red[tid + o]); __syncthreads(); }
    mx = red[0]; __syncthreads();
    float se = 0.f;
    for (int i = tid; i < B_; i += 256) se += expf(s[i * K_ + k] - mx);
    red[tid] = se; __syncthreads();
    for (int o = 128; o; o >>= 1) { if (tid < o) red[tid] += red[tid + o]; __syncthreads(); }
    if (tid == 0) { g_cs[sel * 2 * K_ + k] = mx; g_cs[sel * 2 * K_ + K_ + k] = red[0]; }
}

// ============================================================================
// K5: final S + sigmoid
// ============================================================================
__global__ void k_final(const float* __restrict__ alpha, float* __restrict__ out) {
    int b = blockIdx.x * 256 + threadIdx.x;
    float a = alpha[0];
    float S1 = 0.f, S2 = 0.f;
#pragma unroll
    for (int k = 0; k < K_; k++) {
        S1 += expf(g_s1[b * K_ + k] - g_cs[k]) / g_cs[K_ + k] * g_d1[b * K_ + k];
        S2 += expf(g_s2[b * K_ + k] - g_cs[2 * K_ + k]) / g_cs[3 * K_ + k] * g_d2[b * K_ + k];
    }
    float S = a * S1 + (1.f - a) * S2;
    out[b] = 1.f / (1.f + expf(-S));
}

// ============================================================================
extern "C" void kernel_launch(void* const* d_in, const int* in_sizes, int n_in,
                              void* d_out, int out_size) {
    const int*   users        = (const int*)d_in[0];
    const int*   items        = (const int*)d_in[1];
    const int*   u_items      = (const int*)d_in[2];
    const int*   u_items_mask = (const int*)d_in[3];
    const int*   u_frids      = (const int*)d_in[4];
    const int*   u_frids_mask = (const int*)d_in[5];
    const int*   u_frids_items= (const int*)d_in[6];
    const int*   F_i          = (const int*)d_in[7];
    const float* user_emb     = (const float*)d_in[8];
    const float* item_emb     = (const float*)d_in[9];
    const float* i_class      = (const float*)d_in[10];
    const float* W1  = (const float*)d_in[11];
    const float* b1  = (const float*)d_in[12];
    const float* Wih = (const float*)d_in[13];
    const float* Whh = (const float*)d_in[14];
    const float* bih = (const float*)d_in[15];
    const float* bhh = (const float*)d_in[16];
    const float* W2  = (const float*)d_in[17];
    const float* b2  = (const float*)d_in[18];
    const float* W3  = (const float*)d_in[19];
    const float* b3  = (const float*)d_in[20];
    const float* W4  = (const float*)d_in[21];
    const float* b4  = (const float*)d_in[22];
    const float* W5  = (const float*)d_in[23];
    const float* b5  = (const float*)d_in[24];
    const float* W6  = (const float*)d_in[25];
    const float* b6  = (const float*)d_in[26];
    const float* alpha   = (const float*)d_in[27];
    const float* lambdas = (const float*)d_in[28];

    cudaFuncSetAttribute(k_lstm, cudaFuncAttributeMaxDynamicSharedMemorySize, LSTM_SMEM);
    cudaFuncSetAttribute(k_user, cudaFuncAttributeMaxDynamicSharedMemorySize, USER_SMEM);

    k_precompute<<<(NIP1 + 3) / 4, 256>>>(item_emb, i_class, W1, b1, W3, b3);
    k_lstm<<<B_ / 32, 256, LSTM_SMEM>>>(u_items, u_items_mask, Wih, Whh, bih, bhh);
    k_user<<<B_ / 8, 256, USER_SMEM>>>(users, items, u_frids, u_frids_mask,
                                       u_frids_items, F_i, user_emb, item_emb,
                                       W2, b2, W4, b4, W5, b5, W6, b6, lambdas);
    k_cstat<<<2 * K_, 256>>>();
    k_final<<<B_ / 256, 256>>>(alpha, (float*)d_out);
}

// round 2
// speedup vs baseline: 1.0354x; 1.0354x over previous
#include <cuda_runtime.h>
#include <math.h>

#define B_   4096
#define L_   50
#define K_   10
#define LI_  20
#define D_   64
#define C_   10
#define NIP1 50001

// ---------------- scratch (static device globals; no allocation) -------------
__device__ float g_ju[NIP1 * D_];
__device__ float g_jv[NIP1 * D_];
__device__ float g_hu[B_ * D_];
__device__ float g_s1[B_ * K_];
__device__ float g_s2[B_ * K_];
__device__ float g_d1[B_ * K_];
__device__ float g_d2[B_ * K_];
__device__ float g_cs[4 * K_];   // [0:10) max1, [10:20) sum1, [20:30) max2, [30:40) sum2

__device__ __forceinline__ float wred(float v) {
#pragma unroll
    for (int o = 16; o; o >>= 1) v += __shfl_xor_sync(0xffffffffu, v, o);
    return v;
}
__device__ __forceinline__ float lrelu(float x) { return x >= 0.f ? x : 0.01f * x; }

// packed f32x2 fma (FFMA2) — only reachable via PTX
#define FMA2(d, a, b, c) \
    asm("fma.rn.f32x2 %0, %1, %2, %3;" : "=l"(d) : "l"(a), "l"(b), "l"(c))
#define PACK_DUP(d, x) \
    asm("mov.b64 %0, {%1, %1};" : "=l"(d) : "f"(x))
#define UNPACK2(lo, hi, p) \
    asm("mov.b64 {%0, %1}, %2;" : "=f"(lo), "=f"(hi) : "l"(p))

// ============================================================================
// K1: ju_all = [item_emb | i_class] @ W1 + b1 ; jv_all = same with W3/b3
// ============================================================================
__global__ void k_precompute(const float* __restrict__ item_emb,
                             const float* __restrict__ i_class,
                             const float* __restrict__ W1, const float* __restrict__ b1,
                             const float* __restrict__ W3, const float* __restrict__ b3) {
    __shared__ float W1s[74][64];
    __shared__ float W3s[74][64];
    __shared__ float xs[4][74];
    int tid = threadIdx.x;
    for (int i = tid; i < 74 * 64; i += 256) {
        W1s[i / 64][i % 64] = W1[i];
        W3s[i / 64][i % 64] = W3[i];
    }
    int row0 = blockIdx.x * 4;
    for (int i = tid; i < 4 * 74; i += 256) {
        int rr = i / 74, k = i % 74;
        int row = row0 + rr;
        float v = 0.f;
        if (row < NIP1) v = (k < 64) ? item_emb[row * 64 + k] : i_class[row * 10 + (k - 64)];
        xs[rr][k] = v;
    }
    __syncthreads();
    int r = tid >> 6, c = tid & 63;
    int row = row0 + r;
    if (row < NIP1) {
        float a1 = b1[c], a3 = b3[c];
#pragma unroll
        for (int k = 0; k < 74; k++) {
            float x = xs[r][k];
            a1 = fmaf(x, W1s[k][c], a1);
            a3 = fmaf(x, W3s[k][c], a3);
        }
        g_ju[row * 64 + c] = a1;
        g_jv[row * 64 + c] = a3;
    }
}

// ============================================================================
// K2: LSTM. 128 blocks x 32 rows, 256 threads. FFMA2 (packed f32x2) mainloop.
// Thread (rg=tid/64, cell=tid%64): 8 rows, cols {cell*4+g} in the permuted
// weight layout = gates (i,f,g,o) of cell `cell`. Accumulators are f32x2
// pairs: acc01 = (i,f), acc23 = (g,o). Activation broadcast-packed (a,a).
// ============================================================================
#define LSTM_SMEM ((128*256 + 64*36 + 64*36) * 4 + 32 * L_ * 4)

__global__ void __launch_bounds__(256, 1)
k_lstm(const int* __restrict__ u_items, const int* __restrict__ u_items_mask,
       const float* __restrict__ Wih, const float* __restrict__ Whh,
       const float* __restrict__ bih, const float* __restrict__ bhh) {
    extern __shared__ float sm[];
    float* Wp  = sm;                  // 128*256
    float* xs  = Wp + 128 * 256;      // 64*36
    float* hs  = xs + 64 * 36;        // 64*36
    int*   idxs = (int*)(hs + 64 * 36); // 32*50
    __shared__ int s_max;

    int tid = threadIdx.x;
    int base = blockIdx.x * 32;

    if (tid == 0) s_max = 0;
    // permuted weight stage: Wp[k][cell*4+g] = W[k][cell + 64*g]
    for (int i = tid; i < 128 * 256; i += 256) {
        int k = i >> 8, jp = i & 255;
        int cc = jp >> 2, g = jp & 3;
        int j = cc + 64 * g;
        Wp[i] = (k < 64) ? Wih[k * 256 + j] : Whh[(k - 64) * 256 + j];
    }
    for (int i = tid; i < 64 * 36; i += 256) hs[i] = 0.f;
    for (int i = tid; i < 32 * L_; i += 256) {
        int r = i / L_, t = i % L_;
        idxs[r * L_ + t] = u_items[(base + r) * L_ + t];
    }
    int cell = tid & 63;
    int rg = tid >> 6;
    int msk[8];
    int mm = 0;
#pragma unroll
    for (int rr = 0; rr < 8; rr++) {
        msk[rr] = u_items_mask[base + rg * 8 + rr];
        mm = max(mm, msk[rr]);
    }
    __syncthreads();
    atomicMax(&s_max, mm);
    float bsum[4];
#pragma unroll
    for (int g = 0; g < 4; g++) bsum[g] = bih[cell + 64 * g] + bhh[cell + 64 * g];
    float c_reg[8];
#pragma unroll
    for (int rr = 0; rr < 8; rr++) c_reg[rr] = 0.f;
    __syncthreads();
    int maxm = s_max;

    int grow = tid & 31, gk8 = tid >> 5;   // gather assignment
    int abase = rg * 8;

    for (int t = 0; t < maxm; t++) {
        // gather x_t (transposed into xs[k][row])
        {
            int idx = idxs[grow * L_ + t];
            const float4* src = (const float4*)(g_ju + idx * 64 + gk8 * 8);
            float4 v0 = src[0], v1 = src[1];
            xs[(gk8 * 8 + 0) * 36 + grow] = v0.x;
            xs[(gk8 * 8 + 1) * 36 + grow] = v0.y;
            xs[(gk8 * 8 + 2) * 36 + grow] = v0.z;
            xs[(gk8 * 8 + 3) * 36 + grow] = v0.w;
            xs[(gk8 * 8 + 4) * 36 + grow] = v1.x;
            xs[(gk8 * 8 + 5) * 36 + grow] = v1.y;
            xs[(gk8 * 8 + 6) * 36 + grow] = v1.z;
            xs[(gk8 * 8 + 7) * 36 + grow] = v1.w;
        }
        __syncthreads();

        unsigned long long acc01[8], acc23[8];
#pragma unroll
        for (int rr = 0; rr < 8; rr++) { acc01[rr] = 0ull; acc23[rr] = 0ull; }

        const float* Wx = Wp;
        const float* Wh = Wp + 64 * 256;
#pragma unroll 8
        for (int k = 0; k < 64; k++) {
            ulonglong2 w = *(const ulonglong2*)(Wx + k * 256 + (cell << 2));
            float4 a0 = *(const float4*)(xs + k * 36 + abase);
            float4 a1 = *(const float4*)(xs + k * 36 + abase + 4);
            float ar[8] = {a0.x, a0.y, a0.z, a0.w, a1.x, a1.y, a1.z, a1.w};
#pragma unroll
            for (int rr = 0; rr < 8; rr++) {
                unsigned long long ad;
                PACK_DUP(ad, ar[rr]);
                FMA2(acc01[rr], ad, w.x, acc01[rr]);
                FMA2(acc23[rr], ad, w.y, acc23[rr]);
            }
        }
#pragma unroll 8
        for (int k = 0; k < 64; k++) {
            ulonglong2 w = *(const ulonglong2*)(Wh + k * 256 + (cell << 2));
            float4 a0 = *(const float4*)(hs + k * 36 + abase);
            float4 a1 = *(const float4*)(hs + k * 36 + abase + 4);
            float ar[8] = {a0.x, a0.y, a0.z, a0.w, a1.x, a1.y, a1.z, a1.w};
#pragma unroll
            for (int rr = 0; rr < 8; rr++) {
                unsigned long long ad;
                PACK_DUP(ad, ar[rr]);
                FMA2(acc01[rr], ad, w.x, acc01[rr]);
                FMA2(acc23[rr], ad, w.y, acc23[rr]);
            }
        }
        __syncthreads();   // GEMM reads of hs done before rewrite

#pragma unroll
        for (int rr = 0; rr < 8; rr++) {
            float gi, gf, gg, go;
            UNPACK2(gi, gf, acc01[rr]);
            UNPACK2(gg, go, acc23[rr]);
            gi += bsum[0];
            gf += bsum[1];
            gg += bsum[2];
            go += bsum[3];
            float si = 1.f / (1.f + expf(-gi));
            float sf = 1.f / (1.f + expf(-gf));
            float so = 1.f / (1.f + expf(-go));
            float c = sf * c_reg[rr] + si * tanhf(gg);
            c_reg[rr] = c;
            float h = so * tanhf(c);
            int row = rg * 8 + rr;
            hs[cell * 36 + row] = h;
            if (t == msk[rr] - 1) g_hu[(base + row) * 64 + cell] = h;
        }
        // hs writes ordered before next GEMM by the sync after the next gather
    }
}

// ============================================================================
// K3: per-row user stage. 8 warps = 8 rows per block, grid 512.
// Produces s1,s2 and d{1,2}[b,k] = dot(zsum[b], Fi{1,2}[b,k]).
// ============================================================================
#define USER_SMEM ((192*64*2 + 256 + 8*192) * 4)

__global__ void __launch_bounds__(256)
k_user(const int* __restrict__ users, const int* __restrict__ items,
       const int* __restrict__ u_frids, const int* __restrict__ u_frids_mask,
       const int* __restrict__ u_frids_items, const int* __restrict__ F_i,
       const float* __restrict__ user_emb, const float* __restrict__ item_emb,
       const float* __restrict__ W2, const float* __restrict__ b2,
       const float* __restrict__ W4, const float* __restrict__ b4,
       const float* __restrict__ W5, const float* __restrict__ b5,
       const float* __restrict__ W6, const float* __restrict__ b6,
       const float* __restrict__ lambdas) {
    extern __shared__ float sm[];
    float* W2s = sm;                 // 192*64
    float* W5s = W2s + 192 * 64;     // 192*64
    float* W4s = W5s + 192 * 64;     // 128
    float* W6s = W4s + 128;          // 128
    float* zb  = W6s + 128;          // 8*192

    int tid = threadIdx.x;
    for (int i = tid; i < 192 * 64; i += 256) { W2s[i] = W2[i]; W5s[i] = W5[i]; }
    for (int i = tid; i < 128; i += 256) { W4s[i] = W4[i]; W6s[i] = W6[i]; }
    __syncthreads();

    int w = tid >> 5, lane = tid & 31;
    int row = blockIdx.x * 8 + w;
    int c0 = lane * 2;
    float l0 = lambdas[0], l1 = lambdas[1], l2 = lambdas[2], l3 = lambdas[3];
    float b4v = b4[0], b6v = b6[0];

    int usr = users[row], itm = items[row];
    float2 u2  = *(const float2*)(user_emb + usr * 64 + c0);
    float2 ie2 = *(const float2*)(item_emb + itm * 64 + c0);
    float2 hu2 = *(const float2*)(g_hu + row * 64 + c0);

    float du = wred(u2.x * W4s[c0] + u2.y * W4s[c0 + 1]);

    float at[K_];
#pragma unroll
    for (int k = 0; k < K_; k++) {
        int fid = u_frids[row * K_ + k];
        float2 v2 = *(const float2*)(user_emb + fid * 64 + c0);
        float s = wred(v2.x * W4s[64 + c0] + v2.y * W4s[65 + c0]);
        at[k] = lrelu(du + s + b4v);
    }
    int fm = u_frids_mask[row];
    float mx = -1e30f;
#pragma unroll
    for (int k = 0; k < K_; k++) if (k < fm) mx = fmaxf(mx, at[k]);
    float se = 0.f, ev[K_];
#pragma unroll
    for (int k = 0; k < K_; k++) { ev[k] = (k < fm) ? expf(at[k] - mx) : 0.f; se += ev[k]; }
    float inv = 1.f / (se * (float)fm);

    // su = sum_k (auv_k/fm) * sum_li jv_all[...]
    float sux = 0.f, suy = 0.f;
#pragma unroll
    for (int k = 0; k < K_; k++) {
        if (k < fm) {
            float px = 0.f, py = 0.f;
            const int* ip = u_frids_items + (row * K_ + k) * LI_;
#pragma unroll 4
            for (int li = 0; li < LI_; li++) {
                int idx = ip[li];
                float2 j2 = *(const float2*)(g_jv + idx * 64 + c0);
                px += j2.x; py += j2.y;
            }
            float wk = ev[k] * inv;
            sux = fmaf(wk, px, sux);
            suy = fmaf(wk, py, suy);
        }
    }

    // hui = [hu, ie, hu*ie] @ W2 + b2
    float* z = zb + w * 192;
    z[c0] = hu2.x; z[c0 + 1] = hu2.y;
    z[64 + c0] = ie2.x; z[64 + c0 + 1] = ie2.y;
    z[128 + c0] = hu2.x * ie2.x; z[128 + c0 + 1] = hu2.y * ie2.y;
    __syncwarp();
    float huix = b2[c0], huiy = b2[c0 + 1];
#pragma unroll 8
    for (int k = 0; k < 192; k++) {
        float x = z[k];
        huix = fmaf(x, W2s[k * 64 + c0], huix);
        huiy = fmaf(x, W2s[k * 64 + c0 + 1], huiy);
    }
    __syncwarp();
    // sui = [su, ie, su*ie] @ W5 + b5 (ie slot unchanged)
    z[c0] = sux; z[c0 + 1] = suy;
    z[128 + c0] = sux * ie2.x; z[128 + c0 + 1] = suy * ie2.y;
    __syncwarp();
    float suix = b5[c0], suiy = b5[c0 + 1];
#pragma unroll 8
    for (int k = 0; k < 192; k++) {
        float x = z[k];
        suix = fmaf(x, W5s[k * 64 + c0], suix);
        suiy = fmaf(x, W5s[k * 64 + c0 + 1], suiy);
    }

    float zsx = l0 * hu2.x + l1 * huix + l2 * sux + l3 * suix;
    float zsy = l0 * hu2.y + l1 * huiy + l2 * suy + l3 * suiy;

    float di = wred(ie2.x * W6s[c0] + ie2.y * W6s[c0 + 1]);

#pragma unroll
    for (int s = 0; s < 2; s++) {
#pragma unroll
        for (int k = 0; k < K_; k++) {
            int fi = F_i[(row * 2 + s) * K_ + k];
            float2 f2 = *(const float2*)(item_emb + fi * 64 + c0);
            float sv = wred(f2.x * W6s[64 + c0] + f2.y * W6s[65 + c0]);
            float dv = wred(f2.x * zsx + f2.y * zsy);
            if (lane == 0) {
                float* sp = s ? g_s2 : g_s1;
                float* dp = s ? g_d2 : g_d1;
                sp[row * K_ + k] = lrelu(di + sv + b6v);
                dp[row * K_ + k] = dv;
            }
        }
    }
}

// ============================================================================
// K4: per-column (axis=0) softmax stats for s1/s2. Single-pass online. 20 blocks.
// ============================================================================
__global__ void k_cstat() {
    int sel = blockIdx.x / K_;
    int k = blockIdx.x % K_;
    const float* s = sel ? g_s2 : g_s1;
    __shared__ float rm[256], rs[256];
    int tid = threadIdx.x;
    float m = -1e30f, acc = 0.f;
    for (int i = tid; i < B_; i += 256) {
        float x = s[i * K_ + k];
        float nm = fmaxf(m, x);
        acc = acc * expf(m - nm) + expf(x - nm);
        m = nm;
    }
    rm[tid] = m; rs[tid] = acc;
    __syncthreads();
    for (int o = 128; o; o >>= 1) {
        if (tid < o) {
            float m2 = rm[tid + o], s2v = rs[tid + o];
            float nm = fmaxf(rm[tid], m2);
            rs[tid] = rs[tid] * expf(rm[tid] - nm) + s2v * expf(m2 - nm);
            rm[tid] = nm;
        }
        __syncthreads();
    }
    if (tid == 0) { g_cs[sel * 2 * K_ + k] = rm[0]; g_cs[sel * 2 * K_ + K_ + k] = rs[0]; }
}

// ============================================================================
// K5: final S + sigmoid
// ============================================================================
__global__ void k_final(const float* __restrict__ alpha, float* __restrict__ out) {
    int b = blockIdx.x * 256 + threadIdx.x;
    float a = alpha[0];
    float S1 = 0.f, S2 = 0.f;
#pragma unroll
    for (int k = 0; k < K_; k++) {
        S1 += expf(g_s1[b * K_ + k] - g_cs[k]) / g_cs[K_ + k] * g_d1[b * K_ + k];
        S2 += expf(g_s2[b * K_ + k] - g_cs[2 * K_ + k]) / g_cs[3 * K_ + k] * g_d2[b * K_ + k];
    }
    float S = a * S1 + (1.f - a) * S2;
    out[b] = 1.f / (1.f + expf(-S));
}

// ============================================================================
extern "C" void kernel_launch(void* const* d_in, const int* in_sizes, int n_in,
                              void* d_out, int out_size) {
    const int*   users        = (const int*)d_in[0];
    const int*   items        = (const int*)d_in[1];
    const int*   u_items      = (const int*)d_in[2];
    const int*   u_items_mask = (const int*)d_in[3];
    const int*   u_frids      = (const int*)d_in[4];
    const int*   u_frids_mask = (const int*)d_in[5];
    const int*   u_frids_items= (const int*)d_in[6];
    const int*   F_i          = (const int*)d_in[7];
    const float* user_emb     = (const float*)d_in[8];
    const float* item_emb     = (const float*)d_in[9];
    const float* i_class      = (const float*)d_in[10];
    const float* W1  = (const float*)d_in[11];
    const float* b1  = (const float*)d_in[12];
    const float* Wih = (const float*)d_in[13];
    const float* Whh = (const float*)d_in[14];
    const float* bih = (const float*)d_in[15];
    const float* bhh = (const float*)d_in[16];
    const float* W2  = (const float*)d_in[17];
    const float* b2  = (const float*)d_in[18];
    const float* W3  = (const float*)d_in[19];
    const float* b3  = (const float*)d_in[20];
    const float* W4  = (const float*)d_in[21];
    const float* b4  = (const float*)d_in[22];
    const float* W5  = (const float*)d_in[23];
    const float* b5  = (const float*)d_in[24];
    const float* W6  = (const float*)d_in[25];
    const float* b6  = (const float*)d_in[26];
    const float* alpha   = (const float*)d_in[27];
    const float* lambdas = (const float*)d_in[28];

    cudaFuncSetAttribute(k_lstm, cudaFuncAttributeMaxDynamicSharedMemorySize, LSTM_SMEM);
    cudaFuncSetAttribute(k_user, cudaFuncAttributeMaxDynamicSharedMemorySize, USER_SMEM);

    k_precompute<<<(NIP1 + 3) / 4, 256>>>(item_emb, i_class, W1, b1, W3, b3);
    k_lstm<<<B_ / 32, 256, LSTM_SMEM>>>(u_items, u_items_mask, Wih, Whh, bih, bhh);
    k_user<<<B_ / 8, 256, USER_SMEM>>>(users, items, u_frids, u_frids_mask,
                                       u_frids_items, F_i, user_emb, item_emb,
                                       W2, b2, W4, b4, W5, b5, W6, b6, lambdas);
    k_cstat<<<2 * K_, 256>>>();
    k_final<<<B_ / 256, 256>>>(alpha, (float*)d_out);
}

// round 3
// speedup vs baseline: 1.1098x; 1.0719x over previous
#include <cuda_runtime.h>
#include <math.h>

#define B_   4096
#define L_   50
#define K_   10
#define LI_  20
#define D_   64
#define C_   10
#define NIP1 50001

typedef unsigned long long ull;

// ---------------- scratch (static device globals; no allocation) -------------
__device__ float g_ju1[NIP1 * 256];   // gate-permuted x@Wih with all biases folded
__device__ float g_jv[NIP1 * D_];
__device__ float g_wc[74 * 256];      // (W1@Wih) gate-permuted
__device__ float g_bc[256];           // b1@Wih + bih + bhh, gate-permuted
__device__ float g_hu[B_ * D_];
__device__ float g_s1[B_ * K_];
__device__ float g_s2[B_ * K_];
__device__ float g_d1[B_ * K_];
__device__ float g_d2[B_ * K_];
__device__ float g_cs[4 * K_];

__device__ __forceinline__ float wred(float v) {
#pragma unroll
    for (int o = 16; o; o >>= 1) v += __shfl_xor_sync(0xffffffffu, v, o);
    return v;
}
__device__ __forceinline__ float lrelu(float x) { return x >= 0.f ? x : 0.01f * x; }

// packed f32x2 fma (FFMA2) — only reachable via PTX
#define FMA2(d, a, b, c) \
    asm("fma.rn.f32x2 %0, %1, %2, %3;" : "=l"(d) : "l"(a), "l"(b), "l"(c))
#define PACK_DUP(d, x) \
    asm("mov.b64 %0, {%1, %1};" : "=l"(d) : "f"(x))
#define PACK2(d, lo, hi) \
    asm("mov.b64 %0, {%1, %2};" : "=l"(d) : "f"(lo), "f"(hi))
#define UNPACK2(lo, hi, p) \
    asm("mov.b64 {%0, %1}, %2;" : "=f"(lo), "=f"(hi) : "l"(p))

__device__ __forceinline__ float sigf(float x) {
    return __fdividef(1.f, 1.f + __expf(-x));
}
__device__ __forceinline__ float tanhf_fast(float x) {
    // tanh(x) = 1 - 2/(e^{2x}+1); saturates correctly at +-inf
    return 1.f - __fdividef(2.f, __expf(2.f * x) + 1.f);
}

// ============================================================================
// K0: combine Wc = W1@Wih (gate-permuted), bc = b1@Wih + bih + bhh
// grid 75 x 256 threads. Block k<74 computes row k of Wc; block 74 computes bc.
// ============================================================================
__global__ void k_combine(const float* __restrict__ W1, const float* __restrict__ b1,
                          const float* __restrict__ Wih, const float* __restrict__ bih,
                          const float* __restrict__ bhh) {
    int jp = threadIdx.x;
    int c = jp >> 2, g = jp & 3;
    int j = c + 64 * g;          // original column
    int k = blockIdx.x;
    if (k < 74) {
        float s = 0.f;
#pragma unroll
        for (int m = 0; m < 64; m++)
            s = fmaf(W1[k * 64 + m], __ldg(&Wih[m * 256 + j]), s);
        g_wc[k * 256 + jp] = s;
    } else {
        float s = bih[j] + bhh[j];
#pragma unroll
        for (int m = 0; m < 64; m++)
            s = fmaf(b1[m], __ldg(&Wih[m * 256 + j]), s);
        g_bc[jp] = s;
    }
}

// ============================================================================
// K1: g_ju1[i][jp] = x74[i] @ Wc[:, jp] + bc[jp]   (256 permuted cols)
//     g_jv [i][j]  = x74[i] @ W3[:, j]  + b3[j]
// 32 rows per block (4 subtiles of 8), 256 threads = 8 rows x 32 col-threads.
// FFMA2 over column pairs; activation dup amortized over 5 FFMA2.
// ============================================================================
#define PRE_SMEM ((74*256 + 74*64 + 256 + 64 + 8*76) * 4)

__global__ void __launch_bounds__(256, 1)
k_precompute(const float* __restrict__ item_emb, const float* __restrict__ i_class,
             const float* __restrict__ W3, const float* __restrict__ b3) {
    extern __shared__ float sm[];
    float* Wcs = sm;                 // 74*256
    float* W3s = Wcs + 74 * 256;     // 74*64
    float* bcs = W3s + 74 * 64;      // 256
    float* b3s = bcs + 256;          // 64
    float* xs  = b3s + 64;           // 8*76

    int tid = threadIdx.x;
    for (int i = tid; i < 74 * 256; i += 256) Wcs[i] = g_wc[i];
    for (int i = tid; i < 74 * 64; i += 256) W3s[i] = W3[i];
    bcs[tid] = g_bc[tid];
    if (tid < 64) b3s[tid] = b3[tid];

    int rs = tid >> 5, c = tid & 31;
#pragma unroll 1
    for (int sub = 0; sub < 4; sub++) {
        int row0 = blockIdx.x * 32 + sub * 8;
        __syncthreads();
        for (int i = tid; i < 8 * 74; i += 256) {
            int rr = i / 74, k = i % 74;
            int row = row0 + rr;
            float v = 0.f;
            if (row < NIP1) v = (k < 64) ? item_emb[row * 64 + k] : i_class[row * 10 + (k - 64)];
            xs[rr * 76 + k] = v;
        }
        __syncthreads();
        int row = row0 + rs;
        const ull* bp = (const ull*)&bcs[8 * c];
        ull a0 = bp[0], a1 = bp[1], a2 = bp[2], a3 = bp[3];
        ull jv = *(const ull*)&b3s[2 * c];
#pragma unroll 2
        for (int k = 0; k < 74; k++) {
            float a = xs[rs * 76 + k];
            ull ad; PACK_DUP(ad, a);
            const ull* wp = (const ull*)&Wcs[k * 256 + 8 * c];
            FMA2(a0, ad, wp[0], a0);
            FMA2(a1, ad, wp[1], a1);
            FMA2(a2, ad, wp[2], a2);
            FMA2(a3, ad, wp[3], a3);
            ull w3 = *(const ull*)&W3s[k * 64 + 2 * c];
            FMA2(jv, ad, w3, jv);
        }
        if (row < NIP1) {
            ull* o = (ull*)&g_ju1[row * 256 + 8 * c];
            o[0] = a0; o[1] = a1; o[2] = a2; o[3] = a3;
            *(ull*)&g_jv[row * 64 + 2 * c] = jv;
        }
    }
}

// ============================================================================
// K2: LSTM (h@Whh only; x-part preloaded from g_ju1 as acc init).
// 128 blocks x 32 rows, 256 threads. Thread (rg, cell) does 8 rows x 4 gates.
// Acc pairing: (row 2rp, row 2rp+1) per gate -> activation pairs come free
// from transposed hs; only weights need dup (4 per k, 16 FFMA2 per k).
// ============================================================================
#define LSTM_SMEM ((64*256 + 64*36) * 4 + 32 * L_ * 4)

__global__ void __launch_bounds__(256, 1)
k_lstm(const int* __restrict__ u_items, const int* __restrict__ u_items_mask,
       const float* __restrict__ Whh) {
    extern __shared__ float sm[];
    float* Wp  = sm;                    // 64*256 (gate-permuted Whh)
    float* hs  = Wp + 64 * 256;         // 64*36 (transposed h, padded)
    int*   idxs = (int*)(hs + 64 * 36); // 32*50
    __shared__ int s_max;

    int tid = threadIdx.x;
    int base = blockIdx.x * 32;
    if (tid == 0) s_max = 0;

    for (int i = tid; i < 64 * 256; i += 256) {
        int k = i >> 8, jp = i & 255;
        int cc = jp >> 2, g = jp & 3;
        Wp[i] = Whh[k * 256 + cc + 64 * g];
    }
    for (int i = tid; i < 64 * 36; i += 256) hs[i] = 0.f;
    for (int i = tid; i < 32 * L_; i += 256) {
        int r = i / L_, t = i % L_;
        idxs[r * L_ + t] = u_items[(base + r) * L_ + t];
    }
    int cell = tid & 63;
    int rg = tid >> 6;
    int abase = rg * 8;
    int msk[8];
    int mm = 0;
#pragma unroll
    for (int rr = 0; rr < 8; rr++) {
        msk[rr] = u_items_mask[base + abase + rr];
        mm = max(mm, msk[rr]);
    }
    __syncthreads();
    atomicMax(&s_max, mm);
    float c_reg[8];
#pragma unroll
    for (int rr = 0; rr < 8; rr++) c_reg[rr] = 0.f;
    __syncthreads();
    int maxm = s_max;

    // prefetch x-part for t=0
    float4 p[8];
#pragma unroll
    for (int rr = 0; rr < 8; rr++)
        p[rr] = *(const float4*)&g_ju1[idxs[(abase + rr) * L_] * 256 + (cell << 2)];

    for (int t = 0; t < maxm; t++) {
        // init accumulators from prefetched x-part (+folded biases)
        ull acc[4][4];
#pragma unroll
        for (int rp = 0; rp < 4; rp++) {
            PACK2(acc[rp][0], p[2 * rp].x, p[2 * rp + 1].x);
            PACK2(acc[rp][1], p[2 * rp].y, p[2 * rp + 1].y);
            PACK2(acc[rp][2], p[2 * rp].z, p[2 * rp + 1].z);
            PACK2(acc[rp][3], p[2 * rp].w, p[2 * rp + 1].w);
        }
        // prefetch next step's x-part (hidden under the GEMM)
        if (t + 1 < maxm) {
#pragma unroll
            for (int rr = 0; rr < 8; rr++)
                p[rr] = *(const float4*)&g_ju1[idxs[(abase + rr) * L_ + t + 1] * 256 + (cell << 2)];
        }
        // h @ Whh
#pragma unroll 4
        for (int k = 0; k < 64; k++) {
            float4 wv = *(const float4*)&Wp[k * 256 + (cell << 2)];
            ull w0, w1, w2, w3;
            PACK_DUP(w0, wv.x); PACK_DUP(w1, wv.y);
            PACK_DUP(w2, wv.z); PACK_DUP(w3, wv.w);
            ulonglong2 h01 = *(const ulonglong2*)&hs[k * 36 + abase];
            ulonglong2 h23 = *(const ulonglong2*)&hs[k * 36 + abase + 4];
            FMA2(acc[0][0], h01.x, w0, acc[0][0]);
            FMA2(acc[0][1], h01.x, w1, acc[0][1]);
            FMA2(acc[0][2], h01.x, w2, acc[0][2]);
            FMA2(acc[0][3], h01.x, w3, acc[0][3]);
            FMA2(acc[1][0], h01.y, w0, acc[1][0]);
            FMA2(acc[1][1], h01.y, w1, acc[1][1]);
            FMA2(acc[1][2], h01.y, w2, acc[1][2]);
            FMA2(acc[1][3], h01.y, w3, acc[1][3]);
            FMA2(acc[2][0], h23.x, w0, acc[2][0]);
            FMA2(acc[2][1], h23.x, w1, acc[2][1]);
            FMA2(acc[2][2], h23.x, w2, acc[2][2]);
            FMA2(acc[2][3], h23.x, w3, acc[2][3]);
            FMA2(acc[3][0], h23.y, w0, acc[3][0]);
            FMA2(acc[3][1], h23.y, w1, acc[3][1]);
            FMA2(acc[3][2], h23.y, w2, acc[3][2]);
            FMA2(acc[3][3], h23.y, w3, acc[3][3]);
        }
        __syncthreads();   // hs reads done before rewrite

#pragma unroll
        for (int rp = 0; rp < 4; rp++) {
            float gi0, gi1, gf0, gf1, gg0, gg1, go0, go1;
            UNPACK2(gi0, gi1, acc[rp][0]);
            UNPACK2(gf0, gf1, acc[rp][1]);
            UNPACK2(gg0, gg1, acc[rp][2]);
            UNPACK2(go0, go1, acc[rp][3]);
#pragma unroll
            for (int half = 0; half < 2; half++) {
                int rr = 2 * rp + half;
                float gi = half ? gi1 : gi0;
                float gf = half ? gf1 : gf0;
                float gg = half ? gg1 : gg0;
                float go = half ? go1 : go0;
                float c = sigf(gf) * c_reg[rr] + sigf(gi) * tanhf_fast(gg);
                c_reg[rr] = c;
                float h = sigf(go) * tanhf_fast(c);
                hs[cell * 36 + abase + rr] = h;
                if (t == msk[rr] - 1) g_hu[(base + abase + rr) * 64 + cell] = h;
            }
        }
        __syncthreads();   // hs writes visible before next GEMM
    }
}

// ============================================================================
// K3: per-row user stage. 8 warps = 8 rows per block, grid 512.
// ============================================================================
#define USER_SMEM ((192*64*2 + 256 + 8*192) * 4)

__global__ void __launch_bounds__(256)
k_user(const int* __restrict__ users, const int* __restrict__ items,
       const int* __restrict__ u_frids, const int* __restrict__ u_frids_mask,
       const int* __restrict__ u_frids_items, const int* __restrict__ F_i,
       const float* __restrict__ user_emb, const float* __restrict__ item_emb,
       const float* __restrict__ W2, const float* __restrict__ b2,
       const float* __restrict__ W4, const float* __restrict__ b4,
       const float* __restrict__ W5, const float* __restrict__ b5,
       const float* __restrict__ W6, const float* __restrict__ b6,
       const float* __restrict__ lambdas) {
    extern __shared__ float sm[];
    float* W2s = sm;
    float* W5s = W2s + 192 * 64;
    float* W4s = W5s + 192 * 64;
    float* W6s = W4s + 128;
    float* zb  = W6s + 128;

    int tid = threadIdx.x;
    for (int i = tid; i < 192 * 64; i += 256) { W2s[i] = W2[i]; W5s[i] = W5[i]; }
    for (int i = tid; i < 128; i += 256) { W4s[i] = W4[i]; W6s[i] = W6[i]; }
    __syncthreads();

    int w = tid >> 5, lane = tid & 31;
    int row = blockIdx.x * 8 + w;
    int c0 = lane * 2;
    float l0 = lambdas[0], l1 = lambdas[1], l2 = lambdas[2], l3 = lambdas[3];
    float b4v = b4[0], b6v = b6[0];

    int usr = users[row], itm = items[row];
    float2 u2  = *(const float2*)(user_emb + usr * 64 + c0);
    float2 ie2 = *(const float2*)(item_emb + itm * 64 + c0);
    float2 hu2 = *(const float2*)(g_hu + row * 64 + c0);

    float du = wred(u2.x * W4s[c0] + u2.y * W4s[c0 + 1]);

    float at[K_];
#pragma unroll
    for (int k = 0; k < K_; k++) {
        int fid = u_frids[row * K_ + k];
        float2 v2 = *(const float2*)(user_emb + fid * 64 + c0);
        float s = wred(v2.x * W4s[64 + c0] + v2.y * W4s[65 + c0]);
        at[k] = lrelu(du + s + b4v);
    }
    int fm = u_frids_mask[row];
    float mx = -1e30f;
#pragma unroll
    for (int k = 0; k < K_; k++) if (k < fm) mx = fmaxf(mx, at[k]);
    float se = 0.f, ev[K_];
#pragma unroll
    for (int k = 0; k < K_; k++) { ev[k] = (k < fm) ? expf(at[k] - mx) : 0.f; se += ev[k]; }
    float inv = 1.f / (se * (float)fm);

    float sux = 0.f, suy = 0.f;
#pragma unroll
    for (int k = 0; k < K_; k++) {
        if (k < fm) {
            float px = 0.f, py = 0.f;
            const int* ip = u_frids_items + (row * K_ + k) * LI_;
#pragma unroll 4
            for (int li = 0; li < LI_; li++) {
                int idx = ip[li];
                float2 j2 = *(const float2*)(g_jv + idx * 64 + c0);
                px += j2.x; py += j2.y;
            }
            float wk = ev[k] * inv;
            sux = fmaf(wk, px, sux);
            suy = fmaf(wk, py, suy);
        }
    }

    float* z = zb + w * 192;
    z[c0] = hu2.x; z[c0 + 1] = hu2.y;
    z[64 + c0] = ie2.x; z[64 + c0 + 1] = ie2.y;
    z[128 + c0] = hu2.x * ie2.x; z[128 + c0 + 1] = hu2.y * ie2.y;
    __syncwarp();
    float huix = b2[c0], huiy = b2[c0 + 1];
#pragma unroll 8
    for (int k = 0; k < 192; k++) {
        float x = z[k];
        huix = fmaf(x, W2s[k * 64 + c0], huix);
        huiy = fmaf(x, W2s[k * 64 + c0 + 1], huiy);
    }
    __syncwarp();
    z[c0] = sux; z[c0 + 1] = suy;
    z[128 + c0] = sux * ie2.x; z[128 + c0 + 1] = suy * ie2.y;
    __syncwarp();
    float suix = b5[c0], suiy = b5[c0 + 1];
#pragma unroll 8
    for (int k = 0; k < 192; k++) {
        float x = z[k];
        suix = fmaf(x, W5s[k * 64 + c0], suix);
        suiy = fmaf(x, W5s[k * 64 + c0 + 1], suiy);
    }

    float zsx = l0 * hu2.x + l1 * huix + l2 * sux + l3 * suix;
    float zsy = l0 * hu2.y + l1 * huiy + l2 * suy + l3 * suiy;

    float di = wred(ie2.x * W6s[c0] + ie2.y * W6s[c0 + 1]);

#pragma unroll
    for (int s = 0; s < 2; s++) {
#pragma unroll
        for (int k = 0; k < K_; k++) {
            int fi = F_i[(row * 2 + s) * K_ + k];
            float2 f2 = *(const float2*)(item_emb + fi * 64 + c0);
            float sv = wred(f2.x * W6s[64 + c0] + f2.y * W6s[65 + c0]);
            float dv = wred(f2.x * zsx + f2.y * zsy);
            if (lane == 0) {
                float* sp = s ? g_s2 : g_s1;
                float* dp = s ? g_d2 : g_d1;
                sp[row * K_ + k] = lrelu(di + sv + b6v);
                dp[row * K_ + k] = dv;
            }
        }
    }
}

// ============================================================================
// K4: per-column softmax stats (online), 20 blocks x 1024 threads
// ============================================================================
__global__ void k_cstat() {
    int sel = blockIdx.x / K_;
    int k = blockIdx.x % K_;
    const float* s = sel ? g_s2 : g_s1;
    __shared__ float rm[1024], rs[1024];
    int tid = threadIdx.x;
    float m = -1e30f, acc = 0.f;
    for (int i = tid; i < B_; i += 1024) {
        float x = s[i * K_ + k];
        float nm = fmaxf(m, x);
        acc = acc * expf(m - nm) + expf(x - nm);
        m = nm;
    }
    rm[tid] = m; rs[tid] = acc;
    __syncthreads();
    for (int o = 512; o; o >>= 1) {
        if (tid < o) {
            float m2 = rm[tid + o], s2v = rs[tid + o];
            float nm = fmaxf(rm[tid], m2);
            rs[tid] = rs[tid] * expf(rm[tid] - nm) + s2v * expf(m2 - nm);
            rm[tid] = nm;
        }
        __syncthreads();
    }
    if (tid == 0) { g_cs[sel * 2 * K_ + k] = rm[0]; g_cs[sel * 2 * K_ + K_ + k] = rs[0]; }
}

// ============================================================================
// K5: final S + sigmoid
// ============================================================================
__global__ void k_final(const float* __restrict__ alpha, float* __restrict__ out) {
    int b = blockIdx.x * 256 + threadIdx.x;
    float a = alpha[0];
    float S1 = 0.f, S2 = 0.f;
#pragma unroll
    for (int k = 0; k < K_; k++) {
        S1 += expf(g_s1[b * K_ + k] - g_cs[k]) / g_cs[K_ + k] * g_d1[b * K_ + k];
        S2 += expf(g_s2[b * K_ + k] - g_cs[2 * K_ + k]) / g_cs[3 * K_ + k] * g_d2[b * K_ + k];
    }
    float S = a * S1 + (1.f - a) * S2;
    out[b] = 1.f / (1.f + expf(-S));
}

// ============================================================================
extern "C" void kernel_launch(void* const* d_in, const int* in_sizes, int n_in,
                              void* d_out, int out_size) {
    const int*   users        = (const int*)d_in[0];
    const int*   items        = (const int*)d_in[1];
    const int*   u_items      = (const int*)d_in[2];
    const int*   u_items_mask = (const int*)d_in[3];
    const int*   u_frids      = (const int*)d_in[4];
    const int*   u_frids_mask = (const int*)d_in[5];
    const int*   u_frids_items= (const int*)d_in[6];
    const int*   F_i          = (const int*)d_in[7];
    const float* user_emb     = (const float*)d_in[8];
    const float* item_emb     = (const float*)d_in[9];
    const float* i_class      = (const float*)d_in[10];
    const float* W1  = (const float*)d_in[11];
    const float* b1  = (const float*)d_in[12];
    const float* Wih = (const float*)d_in[13];
    const float* Whh = (const float*)d_in[14];
    const float* bih = (const float*)d_in[15];
    const float* bhh = (const float*)d_in[16];
    const float* W2  = (const float*)d_in[17];
    const float* b2  = (const float*)d_in[18];
    const float* W3  = (const float*)d_in[19];
    const float* b3  = (const float*)d_in[20];
    const float* W4  = (const float*)d_in[21];
    const float* b4  = (const float*)d_in[22];
    const float* W5  = (const float*)d_in[23];
    const float* b5  = (const float*)d_in[24];
    const float* W6  = (const float*)d_in[25];
    const float* b6  = (const float*)d_in[26];
    const float* alpha   = (const float*)d_in[27];
    const float* lambdas = (const float*)d_in[28];

    cudaFuncSetAttribute(k_precompute, cudaFuncAttributeMaxDynamicSharedMemorySize, PRE_SMEM);
    cudaFuncSetAttribute(k_lstm, cudaFuncAttributeMaxDynamicSharedMemorySize, LSTM_SMEM);
    cudaFuncSetAttribute(k_user, cudaFuncAttributeMaxDynamicSharedMemorySize, USER_SMEM);

    k_combine<<<75, 256>>>(W1, b1, Wih, bih, bhh);
    k_precompute<<<(NIP1 + 31) / 32, 256, PRE_SMEM>>>(item_emb, i_class, W3, b3);
    k_lstm<<<B_ / 32, 256, LSTM_SMEM>>>(u_items, u_items_mask, Whh);
    k_user<<<B_ / 8, 256, USER_SMEM>>>(users, items, u_frids, u_frids_mask,
                                       u_frids_items, F_i, user_emb, item_emb,
                                       W2, b2, W4, b4, W5, b5, W6, b6, lambdas);
    k_cstat<<<2 * K_, 1024>>>();
    k_final<<<B_ / 256, 256>>>(alpha, (float*)d_out);
}

// round 4
// speedup vs baseline: 1.4939x; 1.3460x over previous
#include <cuda_runtime.h>
#include <math.h>

#define B_   4096
#define L_   50
#define K_   10
#define LI_  20
#define D_   64
#define C_   10
#define NIP1 50001

typedef unsigned long long ull;

// ---------------- scratch (static device globals; no allocation) -------------
__device__ float g_ju1[NIP1 * 256];   // gate-permuted x@Wih with all biases folded
__device__ float g_jv[NIP1 * D_];
__device__ float g_wc[74 * 256];      // (W1@Wih) gate-permuted
__device__ float g_bc[256];           // b1@Wih + bih + bhh, gate-permuted
__device__ float g_hu[B_ * D_];
__device__ float g_s1[B_ * K_];
__device__ float g_s2[B_ * K_];
__device__ float g_d1[B_ * K_];
__device__ float g_d2[B_ * K_];
__device__ float g_cs[4 * K_];

__device__ __forceinline__ float wred(float v) {
#pragma unroll
    for (int o = 16; o; o >>= 1) v += __shfl_xor_sync(0xffffffffu, v, o);
    return v;
}
__device__ __forceinline__ float lrelu(float x) { return x >= 0.f ? x : 0.01f * x; }

// packed f32x2 fma (FFMA2) — only reachable via PTX
#define FMA2(d, a, b, c) \
    asm("fma.rn.f32x2 %0, %1, %2, %3;" : "=l"(d) : "l"(a), "l"(b), "l"(c))
#define PACK_DUP(d, x) \
    asm("mov.b64 %0, {%1, %1};" : "=l"(d) : "f"(x))
#define PACK2(d, lo, hi) \
    asm("mov.b64 %0, {%1, %2};" : "=l"(d) : "f"(lo), "f"(hi))
#define UNPACK2(lo, hi, p) \
    asm("mov.b64 {%0, %1}, %2;" : "=f"(lo), "=f"(hi) : "l"(p))

__device__ __forceinline__ float sigf(float x) {
    return __fdividef(1.f, 1.f + __expf(-x));
}
__device__ __forceinline__ float tanhf_fast(float x) {
    return 1.f - __fdividef(2.f, __expf(2.f * x) + 1.f);
}

// ============================================================================
// K0: combine Wc = W1@Wih (gate-permuted), bc = b1@Wih + bih + bhh
// ============================================================================
__global__ void k_combine(const float* __restrict__ W1, const float* __restrict__ b1,
                          const float* __restrict__ Wih, const float* __restrict__ bih,
                          const float* __restrict__ bhh) {
    int jp = threadIdx.x;
    int c = jp >> 2, g = jp & 3;
    int j = c + 64 * g;
    int k = blockIdx.x;
    if (k < 74) {
        float s = 0.f;
#pragma unroll
        for (int m = 0; m < 64; m++)
            s = fmaf(W1[k * 64 + m], __ldg(&Wih[m * 256 + j]), s);
        g_wc[k * 256 + jp] = s;
    } else {
        float s = bih[j] + bhh[j];
#pragma unroll
        for (int m = 0; m < 64; m++)
            s = fmaf(b1[m], __ldg(&Wih[m * 256 + j]), s);
        g_bc[jp] = s;
    }
}

// ============================================================================
// K1: g_ju1 = x74 @ Wc + bc (256 permuted cols), g_jv = x74 @ W3 + b3.
// 32 rows per block, 256 threads = 32 col-threads x 8 row-groups x 4 rows each.
// Each weight read (32B) now serves 4 rows -> 4x less crossbar traffic.
// ============================================================================
#define PRE_SMEM ((74*256 + 74*64 + 256 + 64 + 32*76) * 4)

__global__ void __launch_bounds__(256, 1)
k_precompute(const float* __restrict__ item_emb, const float* __restrict__ i_class,
             const float* __restrict__ W3, const float* __restrict__ b3) {
    extern __shared__ float sm[];
    float* Wcs = sm;                 // 74*256
    float* W3s = Wcs + 74 * 256;     // 74*64
    float* bcs = W3s + 74 * 64;      // 256
    float* b3s = bcs + 256;          // 64
    float* xs  = b3s + 64;           // 32*76

    int tid = threadIdx.x;
    for (int i = tid; i < 74 * 256; i += 256) Wcs[i] = g_wc[i];
    for (int i = tid; i < 74 * 64; i += 256) W3s[i] = W3[i];
    bcs[tid] = g_bc[tid];
    if (tid < 64) b3s[tid] = b3[tid];

    int c = tid & 31, rgrp = tid >> 5;
    int row0 = blockIdx.x * 32;
    // stage 32 rows of x74
    for (int i = tid; i < 32 * 74; i += 256) {
        int rr = i / 74, k = i % 74;
        int row = row0 + rr;
        float v = 0.f;
        if (row < NIP1) v = (k < 64) ? item_emb[row * 64 + k] : i_class[row * 10 + (k - 64)];
        xs[rr * 76 + k] = v;
    }
    __syncthreads();

    ull a[4][4], jv[4];
    {
        const ull* bp = (const ull*)&bcs[8 * c];
        ull b0 = bp[0], b1v = bp[1], b2v = bp[2], b3v = bp[3];
        ull jb = *(const ull*)&b3s[2 * c];
#pragma unroll
        for (int r = 0; r < 4; r++) {
            a[r][0] = b0; a[r][1] = b1v; a[r][2] = b2v; a[r][3] = b3v;
            jv[r] = jb;
        }
    }
#pragma unroll 2
    for (int k = 0; k < 74; k++) {
        const ull* wp = (const ull*)&Wcs[k * 256 + 8 * c];
        ull w0 = wp[0], w1 = wp[1], w2 = wp[2], w3 = wp[3];
        ull w3v = *(const ull*)&W3s[k * 64 + 2 * c];
#pragma unroll
        for (int r = 0; r < 4; r++) {
            float av = xs[(rgrp * 4 + r) * 76 + k];
            ull ad; PACK_DUP(ad, av);
            FMA2(a[r][0], ad, w0, a[r][0]);
            FMA2(a[r][1], ad, w1, a[r][1]);
            FMA2(a[r][2], ad, w2, a[r][2]);
            FMA2(a[r][3], ad, w3, a[r][3]);
            FMA2(jv[r], ad, w3v, jv[r]);
        }
    }
#pragma unroll
    for (int r = 0; r < 4; r++) {
        int row = row0 + rgrp * 4 + r;
        if (row < NIP1) {
            ull* o = (ull*)&g_ju1[row * 256 + 8 * c];
            o[0] = a[r][0]; o[1] = a[r][1]; o[2] = a[r][2]; o[3] = a[r][3];
            *(ull*)&g_jv[row * 64 + 2 * c] = jv[r];
        }
    }
}

// ============================================================================
// K2: LSTM (h@Whh only; x-part gathered from g_ju1 as acc init).
// Double-buffered hs -> single barrier per step.
// ============================================================================
#define LSTM_SMEM ((64*256 + 2*64*36) * 4 + 32 * L_ * 4)

__global__ void __launch_bounds__(256, 1)
k_lstm(const int* __restrict__ u_items, const int* __restrict__ u_items_mask,
       const float* __restrict__ Whh) {
    extern __shared__ float sm[];
    float* Wp   = sm;                     // 64*256 (gate-permuted Whh)
    float* hbuf = Wp + 64 * 256;          // 2 x 64*36
    int*   idxs = (int*)(hbuf + 2 * 64 * 36); // 32*50
    __shared__ int s_max;

    int tid = threadIdx.x;
    int base = blockIdx.x * 32;
    if (tid == 0) s_max = 0;

    for (int i = tid; i < 64 * 256; i += 256) {
        int k = i >> 8, jp = i & 255;
        int cc = jp >> 2, g = jp & 3;
        Wp[i] = Whh[k * 256 + cc + 64 * g];
    }
    for (int i = tid; i < 64 * 36; i += 256) hbuf[i] = 0.f;   // buf0 = zeros
    for (int i = tid; i < 32 * L_; i += 256) {
        int r = i / L_, t = i % L_;
        idxs[r * L_ + t] = u_items[(base + r) * L_ + t];
    }
    int cell = tid & 63;
    int rg = tid >> 6;
    int abase = rg * 8;
    int msk[8];
    int mm = 0;
#pragma unroll
    for (int rr = 0; rr < 8; rr++) {
        msk[rr] = u_items_mask[base + abase + rr];
        mm = max(mm, msk[rr]);
    }
    __syncthreads();
    atomicMax(&s_max, mm);
    float c_reg[8];
#pragma unroll
    for (int rr = 0; rr < 8; rr++) c_reg[rr] = 0.f;
    __syncthreads();
    int maxm = s_max;

    // prefetch x-part for t=0
    float4 p[8];
#pragma unroll
    for (int rr = 0; rr < 8; rr++)
        p[rr] = *(const float4*)&g_ju1[idxs[(abase + rr) * L_] * 256 + (cell << 2)];

    for (int t = 0; t < maxm; t++) {
        float* hr = hbuf + (t & 1) * (64 * 36);        // read h_{t-1}
        float* hw = hbuf + ((t + 1) & 1) * (64 * 36);  // write h_t

        ull acc[4][4];
#pragma unroll
        for (int rp = 0; rp < 4; rp++) {
            PACK2(acc[rp][0], p[2 * rp].x, p[2 * rp + 1].x);
            PACK2(acc[rp][1], p[2 * rp].y, p[2 * rp + 1].y);
            PACK2(acc[rp][2], p[2 * rp].z, p[2 * rp + 1].z);
            PACK2(acc[rp][3], p[2 * rp].w, p[2 * rp + 1].w);
        }
        if (t + 1 < maxm) {
#pragma unroll
            for (int rr = 0; rr < 8; rr++)
                p[rr] = *(const float4*)&g_ju1[idxs[(abase + rr) * L_ + t + 1] * 256 + (cell << 2)];
        }
#pragma unroll 4
        for (int k = 0; k < 64; k++) {
            float4 wv = *(const float4*)&Wp[k * 256 + (cell << 2)];
            ull w0, w1, w2, w3;
            PACK_DUP(w0, wv.x); PACK_DUP(w1, wv.y);
            PACK_DUP(w2, wv.z); PACK_DUP(w3, wv.w);
            ulonglong2 h01 = *(const ulonglong2*)&hr[k * 36 + abase];
            ulonglong2 h23 = *(const ulonglong2*)&hr[k * 36 + abase + 4];
            FMA2(acc[0][0], h01.x, w0, acc[0][0]);
            FMA2(acc[0][1], h01.x, w1, acc[0][1]);
            FMA2(acc[0][2], h01.x, w2, acc[0][2]);
            FMA2(acc[0][3], h01.x, w3, acc[0][3]);
            FMA2(acc[1][0], h01.y, w0, acc[1][0]);
            FMA2(acc[1][1], h01.y, w1, acc[1][1]);
            FMA2(acc[1][2], h01.y, w2, acc[1][2]);
            FMA2(acc[1][3], h01.y, w3, acc[1][3]);
            FMA2(acc[2][0], h23.x, w0, acc[2][0]);
            FMA2(acc[2][1], h23.x, w1, acc[2][1]);
            FMA2(acc[2][2], h23.x, w2, acc[2][2]);
            FMA2(acc[2][3], h23.x, w3, acc[2][3]);
            FMA2(acc[3][0], h23.y, w0, acc[3][0]);
            FMA2(acc[3][1], h23.y, w1, acc[3][1]);
            FMA2(acc[3][2], h23.y, w2, acc[3][2]);
            FMA2(acc[3][3], h23.y, w3, acc[3][3]);
        }

#pragma unroll
        for (int rp = 0; rp < 4; rp++) {
            float gi0, gi1, gf0, gf1, gg0, gg1, go0, go1;
            UNPACK2(gi0, gi1, acc[rp][0]);
            UNPACK2(gf0, gf1, acc[rp][1]);
            UNPACK2(gg0, gg1, acc[rp][2]);
            UNPACK2(go0, go1, acc[rp][3]);
#pragma unroll
            for (int half = 0; half < 2; half++) {
                int rr = 2 * rp + half;
                float gi = half ? gi1 : gi0;
                float gf = half ? gf1 : gf0;
                float gg = half ? gg1 : gg0;
                float go = half ? go1 : go0;
                float c = sigf(gf) * c_reg[rr] + sigf(gi) * tanhf_fast(gg);
                c_reg[rr] = c;
                float h = sigf(go) * tanhf_fast(c);
                hw[cell * 36 + abase + rr] = h;
                if (t == msk[rr] - 1) g_hu[(base + abase + rr) * 64 + cell] = h;
            }
        }
        __syncthreads();   // h_t writes visible; also guards buffer reuse
    }
}

// ============================================================================
// K3: per-row user stage. 8 warps = 8 rows per block, grid 512.
// hui/sui GEMVs fused into one FFMA2 pass over interleaved (W2,W5).
// ============================================================================
#define USER_SMEM ((192*128 + 128 + 128 + 8*384) * 4)

__global__ void __launch_bounds__(256)
k_user(const int* __restrict__ users, const int* __restrict__ items,
       const int* __restrict__ u_frids, const int* __restrict__ u_frids_mask,
       const int* __restrict__ u_frids_items, const int* __restrict__ F_i,
       const float* __restrict__ user_emb, const float* __restrict__ item_emb,
       const float* __restrict__ W2, const float* __restrict__ b2,
       const float* __restrict__ W4, const float* __restrict__ b4,
       const float* __restrict__ W5, const float* __restrict__ b5,
       const float* __restrict__ W6, const float* __restrict__ b6,
       const float* __restrict__ lambdas) {
    extern __shared__ float sm[];
    float* Wi  = sm;                 // 192*128 interleaved (W2[k][c], W5[k][c])
    float* W4s = Wi + 192 * 128;     // 128
    float* W6s = W4s + 128;          // 128
    float* zz  = W6s + 128;          // 8 * 384 (paired z2/z5 per row)

    int tid = threadIdx.x;
    for (int i = tid; i < 192 * 64; i += 256) {
        int k = i >> 6, c = i & 63;
        Wi[k * 128 + 2 * c]     = W2[i];
        Wi[k * 128 + 2 * c + 1] = W5[i];
    }
    for (int i = tid; i < 128; i += 256) { W4s[i] = W4[i]; W6s[i] = W6[i]; }
    __syncthreads();

    int w = tid >> 5, lane = tid & 31;
    int row = blockIdx.x * 8 + w;
    int c0 = lane * 2;
    float l0 = lambdas[0], l1 = lambdas[1], l2 = lambdas[2], l3 = lambdas[3];
    float b4v = b4[0], b6v = b6[0];

    int usr = users[row], itm = items[row];
    float2 u2  = *(const float2*)(user_emb + usr * 64 + c0);
    float2 ie2 = *(const float2*)(item_emb + itm * 64 + c0);
    float2 hu2 = *(const float2*)(g_hu + row * 64 + c0);

    float du = wred(u2.x * W4s[c0] + u2.y * W4s[c0 + 1]);

    float at[K_];
#pragma unroll
    for (int k = 0; k < K_; k++) {
        int fid = u_frids[row * K_ + k];
        float2 v2 = *(const float2*)(user_emb + fid * 64 + c0);
        float s = wred(v2.x * W4s[64 + c0] + v2.y * W4s[65 + c0]);
        at[k] = lrelu(du + s + b4v);
    }
    int fm = u_frids_mask[row];
    float mx = -1e30f;
#pragma unroll
    for (int k = 0; k < K_; k++) if (k < fm) mx = fmaxf(mx, at[k]);
    float se = 0.f, ev[K_];
#pragma unroll
    for (int k = 0; k < K_; k++) { ev[k] = (k < fm) ? expf(at[k] - mx) : 0.f; se += ev[k]; }
    float inv = 1.f / (se * (float)fm);

    float sux = 0.f, suy = 0.f;
#pragma unroll
    for (int k = 0; k < K_; k++) {
        if (k < fm) {
            float px = 0.f, py = 0.f;
            const int* ip = u_frids_items + (row * K_ + k) * LI_;
#pragma unroll 4
            for (int li = 0; li < LI_; li++) {
                int idx = ip[li];
                float2 j2 = *(const float2*)(g_jv + idx * 64 + c0);
                px += j2.x; py += j2.y;
            }
            float wk = ev[k] * inv;
            sux = fmaf(wk, px, sux);
            suy = fmaf(wk, py, suy);
        }
    }

    // fused hui/sui: z pairs (z2_k, z5_k); weights interleaved (W2, W5)
    ull* z = (ull*)(zz + w * 384);
    PACK2(z[c0],       hu2.x, sux);
    PACK2(z[c0 + 1],   hu2.y, suy);
    PACK2(z[64 + c0],     ie2.x, ie2.x);
    PACK2(z[64 + c0 + 1], ie2.y, ie2.y);
    PACK2(z[128 + c0],     hu2.x * ie2.x, sux * ie2.x);
    PACK2(z[128 + c0 + 1], hu2.y * ie2.y, suy * ie2.y);
    __syncwarp();
    ull acc0, acc1;
    PACK2(acc0, b2[c0], b5[c0]);
    PACK2(acc1, b2[c0 + 1], b5[c0 + 1]);
#pragma unroll 8
    for (int k = 0; k < 192; k++) {
        ull zk = z[k];
        ulonglong2 wv = *(const ulonglong2*)&Wi[k * 128 + 4 * lane];
        FMA2(acc0, zk, wv.x, acc0);
        FMA2(acc1, zk, wv.y, acc1);
    }
    float huix, suix, huiy, suiy;
    UNPACK2(huix, suix, acc0);
    UNPACK2(huiy, suiy, acc1);

    float zsx = l0 * hu2.x + l1 * huix + l2 * sux + l3 * suix;
    float zsy = l0 * hu2.y + l1 * huiy + l2 * suy + l3 * suiy;

    float di = wred(ie2.x * W6s[c0] + ie2.y * W6s[c0 + 1]);

#pragma unroll
    for (int s = 0; s < 2; s++) {
#pragma unroll
        for (int k = 0; k < K_; k++) {
            int fi = F_i[(row * 2 + s) * K_ + k];
            float2 f2 = *(const float2*)(item_emb + fi * 64 + c0);
            float sv = wred(f2.x * W6s[64 + c0] + f2.y * W6s[65 + c0]);
            float dv = wred(f2.x * zsx + f2.y * zsy);
            if (lane == 0) {
                float* sp = s ? g_s2 : g_s1;
                float* dp = s ? g_d2 : g_d1;
                sp[row * K_ + k] = lrelu(di + sv + b6v);
                dp[row * K_ + k] = dv;
            }
        }
    }
}

// ============================================================================
// K4: per-column softmax stats (online), 20 blocks x 1024 threads
// ============================================================================
__global__ void k_cstat() {
    int sel = blockIdx.x / K_;
    int k = blockIdx.x % K_;
    const float* s = sel ? g_s2 : g_s1;
    __shared__ float rm[1024], rs[1024];
    int tid = threadIdx.x;
    float m = -1e30f, acc = 0.f;
    for (int i = tid; i < B_; i += 1024) {
        float x = s[i * K_ + k];
        float nm = fmaxf(m, x);
        acc = acc * expf(m - nm) + expf(x - nm);
        m = nm;
    }
    rm[tid] = m; rs[tid] = acc;
    __syncthreads();
    for (int o = 512; o; o >>= 1) {
        if (tid < o) {
            float m2 = rm[tid + o], s2v = rs[tid + o];
            float nm = fmaxf(rm[tid], m2);
            rs[tid] = rs[tid] * expf(rm[tid] - nm) + s2v * expf(m2 - nm);
            rm[tid] = nm;
        }
        __syncthreads();
    }
    if (tid == 0) { g_cs[sel * 2 * K_ + k] = rm[0]; g_cs[sel * 2 * K_ + K_ + k] = rs[0]; }
}

// ============================================================================
// K5: final S + sigmoid
// ============================================================================
__global__ void k_final(const float* __restrict__ alpha, float* __restrict__ out) {
    int b = blockIdx.x * 256 + threadIdx.x;
    float a = alpha[0];
    float S1 = 0.f, S2 = 0.f;
#pragma unroll
    for (int k = 0; k < K_; k++) {
        S1 += expf(g_s1[b * K_ + k] - g_cs[k]) / g_cs[K_ + k] * g_d1[b * K_ + k];
        S2 += expf(g_s2[b * K_ + k] - g_cs[2 * K_ + k]) / g_cs[3 * K_ + k] * g_d2[b * K_ + k];
    }
    float S = a * S1 + (1.f - a) * S2;
    out[b] = 1.f / (1.f + expf(-S));
}

// ============================================================================
extern "C" void kernel_launch(void* const* d_in, const int* in_sizes, int n_in,
                              void* d_out, int out_size) {
    const int*   users        = (const int*)d_in[0];
    const int*   items        = (const int*)d_in[1];
    const int*   u_items      = (const int*)d_in[2];
    const int*   u_items_mask = (const int*)d_in[3];
    const int*   u_frids      = (const int*)d_in[4];
    const int*   u_frids_mask = (const int*)d_in[5];
    const int*   u_frids_items= (const int*)d_in[6];
    const int*   F_i          = (const int*)d_in[7];
    const float* user_emb     = (const float*)d_in[8];
    const float* item_emb     = (const float*)d_in[9];
    const float* i_class      = (const float*)d_in[10];
    const float* W1  = (const float*)d_in[11];
    const float* b1  = (const float*)d_in[12];
    const float* Wih = (const float*)d_in[13];
    const float* Whh = (const float*)d_in[14];
    const float* bih = (const float*)d_in[15];
    const float* bhh = (const float*)d_in[16];
    const float* W2  = (const float*)d_in[17];
    const float* b2  = (const float*)d_in[18];
    const float* W3  = (const float*)d_in[19];
    const float* b3  = (const float*)d_in[20];
    const float* W4  = (const float*)d_in[21];
    const float* b4  = (const float*)d_in[22];
    const float* W5  = (const float*)d_in[23];
    const float* b5  = (const float*)d_in[24];
    const float* W6  = (const float*)d_in[25];
    const float* b6  = (const float*)d_in[26];
    const float* alpha   = (const float*)d_in[27];
    const float* lambdas = (const float*)d_in[28];

    cudaFuncSetAttribute(k_precompute, cudaFuncAttributeMaxDynamicSharedMemorySize, PRE_SMEM);
    cudaFuncSetAttribute(k_lstm, cudaFuncAttributeMaxDynamicSharedMemorySize, LSTM_SMEM);
    cudaFuncSetAttribute(k_user, cudaFuncAttributeMaxDynamicSharedMemorySize, USER_SMEM);

    k_combine<<<75, 256>>>(W1, b1, Wih, bih, bhh);
    k_precompute<<<(NIP1 + 31) / 32, 256, PRE_SMEM>>>(item_emb, i_class, W3, b3);
    k_lstm<<<B_ / 32, 256, LSTM_SMEM>>>(u_items, u_items_mask, Whh);
    k_user<<<B_ / 8, 256, USER_SMEM>>>(users, items, u_frids, u_frids_mask,
                                       u_frids_items, F_i, user_emb, item_emb,
                                       W2, b2, W4, b4, W5, b5, W6, b6, lambdas);
    k_cstat<<<2 * K_, 1024>>>();
    k_final<<<B_ / 256, 256>>>(alpha, (float*)d_out);
}

// round 5
// speedup vs baseline: 1.8067x; 1.2094x over previous
#include <cuda_runtime.h>
#include <math.h>

#define B_   4096
#define L_   50
#define K_   10
#define LI_  20
#define D_   64
#define C_   10
#define NIP1 50001
#define NSEG 256          // B_/16 segments for the persistent LSTM

typedef unsigned long long ull;

// ---------------- scratch (static device globals; no allocation) -------------
__device__ float g_ju1[NIP1 * 256];   // gate-permuted x@Wih with all biases folded
__device__ float g_jv[NIP1 * D_];
__device__ float g_wc[74 * 256];      // (W1@Wih) gate-permuted
__device__ float g_bc[256];           // b1@Wih + bih + bhh, gate-permuted
__device__ float g_hu[B_ * D_];
__device__ float g_s1[B_ * K_];
__device__ float g_s2[B_ * K_];
__device__ float g_d1[B_ * K_];
__device__ float g_d2[B_ * K_];
__device__ float g_cs[4 * K_];
__device__ int   g_order[B_];
__device__ int   g_ctr;

__device__ __forceinline__ float lrelu(float x) { return x >= 0.f ? x : 0.01f * x; }

// packed f32x2 fma (FFMA2) — only reachable via PTX
#define FMA2(d, a, b, c) \
    asm("fma.rn.f32x2 %0, %1, %2, %3;" : "=l"(d) : "l"(a), "l"(b), "l"(c))
#define PACK_DUP(d, x) \
    asm("mov.b64 %0, {%1, %1};" : "=l"(d) : "f"(x))
#define PACK2(d, lo, hi) \
    asm("mov.b64 %0, {%1, %2};" : "=l"(d) : "f"(lo), "f"(hi))
#define UNPACK2(lo, hi, p) \
    asm("mov.b64 {%0, %1}, %2;" : "=f"(lo), "=f"(hi) : "l"(p))

__device__ __forceinline__ float sigf(float x) {
    return __fdividef(1.f, 1.f + __expf(-x));
}
__device__ __forceinline__ float tanhf_fast(float x) {
    return 1.f - __fdividef(2.f, __expf(2.f * x) + 1.f);
}

// ============================================================================
// K0: combine Wc = W1@Wih (gate-permuted), bc = b1@Wih + bih + bhh
// ============================================================================
__global__ void k_combine(const float* __restrict__ W1, const float* __restrict__ b1,
                          const float* __restrict__ Wih, const float* __restrict__ bih,
                          const float* __restrict__ bhh) {
    int jp = threadIdx.x;
    int c = jp >> 2, g = jp & 3;
    int j = c + 64 * g;
    int k = blockIdx.x;
    if (k < 74) {
        float s = 0.f;
#pragma unroll
        for (int m = 0; m < 64; m++)
            s = fmaf(W1[k * 64 + m], __ldg(&Wih[m * 256 + j]), s);
        g_wc[k * 256 + jp] = s;
    } else {
        float s = bih[j] + bhh[j];
#pragma unroll
        for (int m = 0; m < 64; m++)
            s = fmaf(b1[m], __ldg(&Wih[m * 256 + j]), s);
        g_bc[jp] = s;
    }
}

// ============================================================================
// K0b: counting sort of rows by u_items_mask, DESCENDING. Also resets g_ctr.
// Single block, 1024 threads. Per-row results are independent of within-bin
// order, so atomicAdd ordering does not affect outputs.
// ============================================================================
__global__ void k_sort(const int* __restrict__ mask) {
    __shared__ int cnt[64], off[64];
    int tid = threadIdx.x;
    if (tid < 64) cnt[tid] = 0;
    __syncthreads();
    for (int i = tid; i < B_; i += 1024) atomicAdd(&cnt[mask[i]], 1);
    __syncthreads();
    if (tid == 0) {
        g_ctr = 0;
        int run = 0;
        for (int m = 50; m >= 1; m--) { off[m] = run; run += cnt[m]; }
    }
    __syncthreads();
    if (tid < 64) cnt[tid] = 0;
    __syncthreads();
    for (int i = tid; i < B_; i += 1024) {
        int m = mask[i];
        int pos = off[m] + atomicAdd(&cnt[m], 1);
        g_order[pos] = i;
    }
}

// ============================================================================
// K1: g_ju1 = x74 @ Wc + bc (256 permuted cols), g_jv = x74 @ W3 + b3.
// 32 rows per block, 256 threads = 32 col-threads x 8 row-groups x 4 rows each.
// ============================================================================
#define PRE_SMEM ((74*256 + 74*64 + 256 + 64 + 32*76) * 4)

__global__ void __launch_bounds__(256, 1)
k_precompute(const float* __restrict__ item_emb, const float* __restrict__ i_class,
             const float* __restrict__ W3, const float* __restrict__ b3) {
    extern __shared__ float sm[];
    float* Wcs = sm;                 // 74*256
    float* W3s = Wcs + 74 * 256;     // 74*64
    float* bcs = W3s + 74 * 64;      // 256
    float* b3s = bcs + 256;          // 64
    float* xs  = b3s + 64;           // 32*76

    int tid = threadIdx.x;
    for (int i = tid; i < 74 * 256; i += 256) Wcs[i] = g_wc[i];
    for (int i = tid; i < 74 * 64; i += 256) W3s[i] = W3[i];
    bcs[tid] = g_bc[tid];
    if (tid < 64) b3s[tid] = b3[tid];

    int c = tid & 31, rgrp = tid >> 5;
    int row0 = blockIdx.x * 32;
    for (int i = tid; i < 32 * 74; i += 256) {
        int rr = i / 74, k = i % 74;
        int row = row0 + rr;
        float v = 0.f;
        if (row < NIP1) v = (k < 64) ? item_emb[row * 64 + k] : i_class[row * 10 + (k - 64)];
        xs[rr * 76 + k] = v;
    }
    __syncthreads();

    ull a[4][4], jv[4];
    {
        const ull* bp = (const ull*)&bcs[8 * c];
        ull b0 = bp[0], b1v = bp[1], b2v = bp[2], b3v = bp[3];
        ull jb = *(const ull*)&b3s[2 * c];
#pragma unroll
        for (int r = 0; r < 4; r++) {
            a[r][0] = b0; a[r][1] = b1v; a[r][2] = b2v; a[r][3] = b3v;
            jv[r] = jb;
        }
    }
#pragma unroll 2
    for (int k = 0; k < 74; k++) {
        const ull* wp = (const ull*)&Wcs[k * 256 + 8 * c];
        ull w0 = wp[0], w1 = wp[1], w2 = wp[2], w3 = wp[3];
        ull w3v = *(const ull*)&W3s[k * 64 + 2 * c];
#pragma unroll
        for (int r = 0; r < 4; r++) {
            float av = xs[(rgrp * 4 + r) * 76 + k];
            ull ad; PACK_DUP(ad, av);
            FMA2(a[r][0], ad, w0, a[r][0]);
            FMA2(a[r][1], ad, w1, a[r][1]);
            FMA2(a[r][2], ad, w2, a[r][2]);
            FMA2(a[r][3], ad, w3, a[r][3]);
            FMA2(jv[r], ad, w3v, jv[r]);
        }
    }
#pragma unroll
    for (int r = 0; r < 4; r++) {
        int row = row0 + rgrp * 4 + r;
        if (row < NIP1) {
            ull* o = (ull*)&g_ju1[row * 256 + 8 * c];
            o[0] = a[r][0]; o[1] = a[r][1]; o[2] = a[r][2]; o[3] = a[r][3];
            *(ull*)&g_jv[row * 64 + 2 * c] = jv[r];
        }
    }
}

// ============================================================================
// K2: persistent sorted LSTM. 148 blocks x 256 threads pull 16-row segments
// (sorted by mask desc) via atomic counter. Each segment runs only its own
// max mask (LPT balance). Thread (rg 0-3, cell 0-63) does 4 rows x 4 gates.
// ============================================================================
#define LSTM_SMEM ((64*256 + 2*64*20) * 4 + (16*50 + 32) * 4)

__global__ void __launch_bounds__(256, 1)
k_lstm(const int* __restrict__ u_items, const int* __restrict__ u_items_mask,
       const float* __restrict__ Whh) {
    extern __shared__ float sm[];
    float* Wp   = sm;                       // 64*256 gate-permuted Whh
    float* hbuf = Wp + 64 * 256;            // 2 x 64*20
    int*   idxs = (int*)(hbuf + 2 * 64 * 20); // 16*50
    int*   rows_s = idxs + 16 * 50;         // 16
    int*   msk_s  = rows_s + 16;            // 16
    __shared__ int s_seg;

    int tid = threadIdx.x;
    for (int i = tid; i < 64 * 256; i += 256) {
        int k = i >> 8, jp = i & 255;
        Wp[i] = Whh[k * 256 + (jp >> 2) + 64 * (jp & 3)];
    }
    int cell = tid & 63;
    int rg = tid >> 6;
    int abase = rg * 4;

    while (true) {
        __syncthreads();                       // s_seg reuse guard
        if (tid == 0) s_seg = atomicAdd(&g_ctr, 1);
        __syncthreads();
        int seg = s_seg;
        if (seg >= NSEG) break;

        if (tid < 16) {
            int orow = g_order[seg * 16 + tid];
            rows_s[tid] = orow;
            msk_s[tid] = u_items_mask[orow];
        }
        for (int i = tid; i < 64 * 20; i += 256) hbuf[i] = 0.f;  // buf0 = h_{-1}=0
        __syncthreads();
        int maxm = msk_s[0];                   // sorted desc -> first is max
        for (int i = tid; i < 16 * 50; i += 256) {
            int r = i / 50, t = i - r * 50;
            if (t < maxm) idxs[i] = u_items[rows_s[r] * 50 + t];
        }
        int msk[4]; float c_reg[4]; int orw[4];
#pragma unroll
        for (int rr = 0; rr < 4; rr++) {
            msk[rr] = msk_s[abase + rr];
            orw[rr] = rows_s[abase + rr];
            c_reg[rr] = 0.f;
        }
        __syncthreads();

        float4 p[4];
#pragma unroll
        for (int rr = 0; rr < 4; rr++)
            p[rr] = *(const float4*)&g_ju1[idxs[(abase + rr) * 50] * 256 + (cell << 2)];

        for (int t = 0; t < maxm; t++) {
            float* hr = hbuf + (t & 1) * 1280;
            float* hw = hbuf + ((t + 1) & 1) * 1280;

            ull acc[2][4];
            PACK2(acc[0][0], p[0].x, p[1].x);
            PACK2(acc[0][1], p[0].y, p[1].y);
            PACK2(acc[0][2], p[0].z, p[1].z);
            PACK2(acc[0][3], p[0].w, p[1].w);
            PACK2(acc[1][0], p[2].x, p[3].x);
            PACK2(acc[1][1], p[2].y, p[3].y);
            PACK2(acc[1][2], p[2].z, p[3].z);
            PACK2(acc[1][3], p[2].w, p[3].w);

            if (t + 1 < maxm) {
#pragma unroll
                for (int rr = 0; rr < 4; rr++)
                    p[rr] = *(const float4*)&g_ju1[idxs[(abase + rr) * 50 + t + 1] * 256 + (cell << 2)];
            }
#pragma unroll 4
            for (int k = 0; k < 64; k++) {
                float4 wv = *(const float4*)&Wp[k * 256 + (cell << 2)];
                ull w0, w1, w2, w3;
                PACK_DUP(w0, wv.x); PACK_DUP(w1, wv.y);
                PACK_DUP(w2, wv.z); PACK_DUP(w3, wv.w);
                ulonglong2 hp = *(const ulonglong2*)&hr[k * 20 + abase];
                FMA2(acc[0][0], hp.x, w0, acc[0][0]);
                FMA2(acc[0][1], hp.x, w1, acc[0][1]);
                FMA2(acc[0][2], hp.x, w2, acc[0][2]);
                FMA2(acc[0][3], hp.x, w3, acc[0][3]);
                FMA2(acc[1][0], hp.y, w0, acc[1][0]);
                FMA2(acc[1][1], hp.y, w1, acc[1][1]);
                FMA2(acc[1][2], hp.y, w2, acc[1][2]);
                FMA2(acc[1][3], hp.y, w3, acc[1][3]);
            }

#pragma unroll
            for (int rp = 0; rp < 2; rp++) {
                float gi0, gi1, gf0, gf1, gg0, gg1, go0, go1;
                UNPACK2(gi0, gi1, acc[rp][0]);
                UNPACK2(gf0, gf1, acc[rp][1]);
                UNPACK2(gg0, gg1, acc[rp][2]);
                UNPACK2(go0, go1, acc[rp][3]);
#pragma unroll
                for (int half = 0; half < 2; half++) {
                    int rr = 2 * rp + half;
                    float gi = half ? gi1 : gi0;
                    float gf = half ? gf1 : gf0;
                    float gg = half ? gg1 : gg0;
                    float go = half ? go1 : go0;
                    float c = sigf(gf) * c_reg[rr] + sigf(gi) * tanhf_fast(gg);
                    c_reg[rr] = c;
                    float h = sigf(go) * tanhf_fast(c);
                    hw[cell * 20 + abase + rr] = h;
                    if (t == msk[rr] - 1) g_hu[orw[rr] * 64 + cell] = h;
                }
            }
            __syncthreads();
        }
    }
}

// ============================================================================
// K3: per-row user stage. 16 warps = 16 rows per block, grid 256.
// Gathers fully unrolled (max MLP); all warp reductions interleaved.
// ============================================================================
#define USER_SMEM ((192*128 + 128 + 128 + 16*384) * 4)

__global__ void __launch_bounds__(512)
k_user(const int* __restrict__ users, const int* __restrict__ items,
       const int* __restrict__ u_frids, const int* __restrict__ u_frids_mask,
       const int* __restrict__ u_frids_items, const int* __restrict__ F_i,
       const float* __restrict__ user_emb, const float* __restrict__ item_emb,
       const float* __restrict__ W2, const float* __restrict__ b2,
       const float* __restrict__ W4, const float* __restrict__ b4,
       const float* __restrict__ W5, const float* __restrict__ b5,
       const float* __restrict__ W6, const float* __restrict__ b6,
       const float* __restrict__ lambdas) {
    extern __shared__ float sm[];
    float* Wi  = sm;                 // 192*128 interleaved (W2[k][c], W5[k][c])
    float* W4s = Wi + 192 * 128;     // 128
    float* W6s = W4s + 128;          // 128
    float* zz  = W6s + 128;          // 16 * 384

    int tid = threadIdx.x;
    for (int i = tid; i < 192 * 64; i += 512) {
        int k = i >> 6, c = i & 63;
        Wi[k * 128 + 2 * c]     = W2[i];
        Wi[k * 128 + 2 * c + 1] = W5[i];
    }
    if (tid < 128) W4s[tid] = W4[tid];
    else if (tid < 256) W6s[tid - 128] = W6[tid - 128];
    __syncthreads();

    int w = tid >> 5, lane = tid & 31;
    int row = blockIdx.x * 16 + w;
    int c0 = lane * 2;
    float l0 = lambdas[0], l1 = lambdas[1], l2 = lambdas[2], l3 = lambdas[3];
    float b4v = b4[0], b6v = b6[0];

    int usr = users[row], itm = items[row];
    float2 u2  = *(const float2*)(user_emb + usr * 64 + c0);
    float2 ie2 = *(const float2*)(item_emb + itm * 64 + c0);
    float2 hu2 = *(const float2*)(g_hu + row * 64 + c0);

    // ---- jv gather for all K friends (full MLP) ----
    float px[K_], py[K_];
#pragma unroll
    for (int k = 0; k < K_; k++) { px[k] = 0.f; py[k] = 0.f; }
    const int* ip = u_frids_items + row * (K_ * LI_);
#pragma unroll
    for (int k = 0; k < K_; k++) {
#pragma unroll
        for (int li = 0; li < LI_; li++) {
            int idx = ip[k * LI_ + li];
            float2 j2 = *(const float2*)(g_jv + idx * 64 + c0);
            px[k] += j2.x; py[k] += j2.y;
        }
    }

    // ---- attention partials (du + 10 friends), interleaved butterfly ----
    float du_p = u2.x * W4s[c0] + u2.y * W4s[c0 + 1];
    float at_p[K_];
#pragma unroll
    for (int k = 0; k < K_; k++) {
        int fid = u_frids[row * K_ + k];
        float2 v2 = *(const float2*)(user_emb + fid * 64 + c0);
        at_p[k] = v2.x * W4s[64 + c0] + v2.y * W4s[65 + c0];
    }
#pragma unroll
    for (int o = 16; o; o >>= 1) {
        du_p += __shfl_xor_sync(0xffffffffu, du_p, o);
#pragma unroll
        for (int k = 0; k < K_; k++) at_p[k] += __shfl_xor_sync(0xffffffffu, at_p[k], o);
    }
    int fm = u_frids_mask[row];
    float at[K_];
#pragma unroll
    for (int k = 0; k < K_; k++) at[k] = lrelu(du_p + at_p[k] + b4v);
    float mx = -1e30f;
#pragma unroll
    for (int k = 0; k < K_; k++) if (k < fm) mx = fmaxf(mx, at[k]);
    float se = 0.f, ev[K_];
#pragma unroll
    for (int k = 0; k < K_; k++) { ev[k] = (k < fm) ? expf(at[k] - mx) : 0.f; se += ev[k]; }
    float inv = 1.f / (se * (float)fm);

    float sux = 0.f, suy = 0.f;
#pragma unroll
    for (int k = 0; k < K_; k++) {
        float wk = ev[k] * inv;   // 0 for masked
        sux = fmaf(wk, px[k], sux);
        suy = fmaf(wk, py[k], suy);
    }

    // ---- fused hui/sui GEMV ----
    ull* z = (ull*)(zz + w * 384);
    PACK2(z[c0],       hu2.x, sux);
    PACK2(z[c0 + 1],   hu2.y, suy);
    PACK2(z[64 + c0],     ie2.x, ie2.x);
    PACK2(z[64 + c0 + 1], ie2.y, ie2.y);
    PACK2(z[128 + c0],     hu2.x * ie2.x, sux * ie2.x);
    PACK2(z[128 + c0 + 1], hu2.y * ie2.y, suy * ie2.y);
    __syncwarp();
    ull acc0, acc1;
    PACK2(acc0, b2[c0], b5[c0]);
    PACK2(acc1, b2[c0 + 1], b5[c0 + 1]);
#pragma unroll 8
    for (int k = 0; k < 192; k++) {
        ull zk = z[k];
        ulonglong2 wv = *(const ulonglong2*)&Wi[k * 128 + 4 * lane];
        FMA2(acc0, zk, wv.x, acc0);
        FMA2(acc1, zk, wv.y, acc1);
    }
    float huix, suix, huiy, suiy;
    UNPACK2(huix, suix, acc0);
    UNPACK2(huiy, suiy, acc1);

    float zsx = l0 * hu2.x + l1 * huix + l2 * sux + l3 * suix;
    float zsy = l0 * hu2.y + l1 * huiy + l2 * suy + l3 * suiy;

    // ---- di + F_i phase: 1 + 2*10*2 reductions, interleaved per s ----
    float di_p = ie2.x * W6s[c0] + ie2.y * W6s[c0 + 1];
#pragma unroll
    for (int o = 16; o; o >>= 1) di_p += __shfl_xor_sync(0xffffffffu, di_p, o);

#pragma unroll
    for (int s = 0; s < 2; s++) {
        float sp[K_], dp[K_];
#pragma unroll
        for (int k = 0; k < K_; k++) {
            int fi = F_i[(row * 2 + s) * K_ + k];
            float2 f2 = *(const float2*)(item_emb + fi * 64 + c0);
            sp[k] = f2.x * W6s[64 + c0] + f2.y * W6s[65 + c0];
            dp[k] = f2.x * zsx + f2.y * zsy;
        }
#pragma unroll
        for (int o = 16; o; o >>= 1) {
#pragma unroll
            for (int k = 0; k < K_; k++) {
                sp[k] += __shfl_xor_sync(0xffffffffu, sp[k], o);
                dp[k] += __shfl_xor_sync(0xffffffffu, dp[k], o);
            }
        }
        if (lane == 0) {
            float* spo = s ? g_s2 : g_s1;
            float* dpo = s ? g_d2 : g_d1;
#pragma unroll
            for (int k = 0; k < K_; k++) {
                spo[row * K_ + k] = lrelu(di_p + sp[k] + b6v);
                dpo[row * K_ + k] = dp[k];
            }
        }
    }
}

// ============================================================================
// K4: per-column softmax stats (online), 20 blocks x 1024 threads
// ============================================================================
__global__ void k_cstat() {
    int sel = blockIdx.x / K_;
    int k = blockIdx.x % K_;
    const float* s = sel ? g_s2 : g_s1;
    __shared__ float rm[1024], rs[1024];
    int tid = threadIdx.x;
    float m = -1e30f, acc = 0.f;
    for (int i = tid; i < B_; i += 1024) {
        float x = s[i * K_ + k];
        float nm = fmaxf(m, x);
        acc = acc * expf(m - nm) + expf(x - nm);
        m = nm;
    }
    rm[tid] = m; rs[tid] = acc;
    __syncthreads();
    for (int o = 512; o; o >>= 1) {
        if (tid < o) {
            float m2 = rm[tid + o], s2v = rs[tid + o];
            float nm = fmaxf(rm[tid], m2);
            rs[tid] = rs[tid] * expf(rm[tid] - nm) + s2v * expf(m2 - nm);
            rm[tid] = nm;
        }
        __syncthreads();
    }
    if (tid == 0) { g_cs[sel * 2 * K_ + k] = rm[0]; g_cs[sel * 2 * K_ + K_ + k] = rs[0]; }
}

// ============================================================================
// K5: final S + sigmoid
// ============================================================================
__global__ void k_final(const float* __restrict__ alpha, float* __restrict__ out) {
    int b = blockIdx.x * 256 + threadIdx.x;
    float a = alpha[0];
    float S1 = 0.f, S2 = 0.f;
#pragma unroll
    for (int k = 0; k < K_; k++) {
        S1 += expf(g_s1[b * K_ + k] - g_cs[k]) / g_cs[K_ + k] * g_d1[b * K_ + k];
        S2 += expf(g_s2[b * K_ + k] - g_cs[2 * K_ + k]) / g_cs[3 * K_ + k] * g_d2[b * K_ + k];
    }
    float S = a * S1 + (1.f - a) * S2;
    out[b] = 1.f / (1.f + expf(-S));
}

// ============================================================================
extern "C" void kernel_launch(void* const* d_in, const int* in_sizes, int n_in,
                              void* d_out, int out_size) {
    const int*   users        = (const int*)d_in[0];
    const int*   items        = (const int*)d_in[1];
    const int*   u_items      = (const int*)d_in[2];
    const int*   u_items_mask = (const int*)d_in[3];
    const int*   u_frids      = (const int*)d_in[4];
    const int*   u_frids_mask = (const int*)d_in[5];
    const int*   u_frids_items= (const int*)d_in[6];
    const int*   F_i          = (const int*)d_in[7];
    const float* user_emb     = (const float*)d_in[8];
    const float* item_emb     = (const float*)d_in[9];
    const float* i_class      = (const float*)d_in[10];
    const float* W1  = (const float*)d_in[11];
    const float* b1  = (const float*)d_in[12];
    const float* Wih = (const float*)d_in[13];
    const float* Whh = (const float*)d_in[14];
    const float* bih = (const float*)d_in[15];
    const float* bhh = (const float*)d_in[16];
    const float* W2  = (const float*)d_in[17];
    const float* b2  = (const float*)d_in[18];
    const float* W3  = (const float*)d_in[19];
    const float* b3  = (const float*)d_in[20];
    const float* W4  = (const float*)d_in[21];
    const float* b4  = (const float*)d_in[22];
    const float* W5  = (const float*)d_in[23];
    const float* b5  = (const float*)d_in[24];
    const float* W6  = (const float*)d_in[25];
    const float* b6  = (const float*)d_in[26];
    const float* alpha   = (const float*)d_in[27];
    const float* lambdas = (const float*)d_in[28];

    cudaFuncSetAttribute(k_precompute, cudaFuncAttributeMaxDynamicSharedMemorySize, PRE_SMEM);
    cudaFuncSetAttribute(k_lstm, cudaFuncAttributeMaxDynamicSharedMemorySize, LSTM_SMEM);
    cudaFuncSetAttribute(k_user, cudaFuncAttributeMaxDynamicSharedMemorySize, USER_SMEM);

    k_combine<<<75, 256>>>(W1, b1, Wih, bih, bhh);
    k_sort<<<1, 1024>>>(u_items_mask);
    k_precompute<<<(NIP1 + 31) / 32, 256, PRE_SMEM>>>(item_emb, i_class, W3, b3);
    k_lstm<<<148, 256, LSTM_SMEM>>>(u_items, u_items_mask, Whh);
    k_user<<<B_ / 16, 512, USER_SMEM>>>(users, items, u_frids, u_frids_mask,
                                        u_frids_items, F_i, user_emb, item_emb,
                                        W2, b2, W4, b4, W5, b5, W6, b6, lambdas);
    k_cstat<<<2 * K_, 1024>>>();
    k_final<<<B_ / 256, 256>>>(alpha, (float*)d_out);
}